// round 5
// baseline (speedup 1.0000x reference)
#include <cuda_runtime.h>
#include <cuda_bf16.h>
#include <math.h>
#include <stdint.h>

#define BSZ 8
#define LQ 8192
#define NTOK (BSZ*LQ)
#define NC 64
#define CL 128
#define TP 136                      // padded tile row (bf16 elems)
#define TILE_B (128*TP*2)           // tile bytes = 34816

// ---------------- scratch (device globals; no allocations allowed) ----------
__device__ float g_at[(size_t)NTOK*128];
__device__ float g_bt[(size_t)NTOK*128];
__device__ float g_hf[(size_t)NTOK*128];
__device__ float g_hb[(size_t)NTOK*128];
__device__ float g_cfA[BSZ*NC*128], g_cfB[BSZ*NC*128];
__device__ float g_cbA[BSZ*NC*128], g_cbB[BSZ*NC*128];
__device__ float g_carF[BSZ*NC*128], g_carB[BSZ*NC*128];
__device__ float g_scal[BSZ*6];
// pre-split transposed weight tiles: 13 tiles of [128][TP] bf16, hi and lo
__device__ __align__(16) __nv_bfloat16 g_whi[13*128*TP];
__device__ __align__(16) __nv_bfloat16 g_wlo[13*128*TP];

// ---------------- helpers ---------------------------------------------------
__device__ __forceinline__ float warp_allred(float v){
#pragma unroll
    for (int o=16;o>0;o>>=1) v += __shfl_xor_sync(0xffffffffu, v, o);
    return v;
}
__device__ __forceinline__ float sigmoidf_(float z){
    return __fdividef(1.f, 1.f + __expf(-z));
}
__device__ __forceinline__ float gelu_tanh(float v){
    float t;
    asm("tanh.approx.f32 %0, %1;" : "=f"(t) : "f"(0.7978845608028654f * fmaf(0.044715f*v, v*v, v)));
    return 0.5f*v*(1.f+t);
}
__device__ __forceinline__ void split_store(__nv_bfloat16* hi, __nv_bfloat16* lo,
                                            int off, float v){
    __nv_bfloat16 h = __float2bfloat16(v);
    hi[off] = h;
    lo[off] = __float2bfloat16(v - __bfloat162float(h));
}

// mma.sync m16n8k16 bf16 -> f32
__device__ __forceinline__ void mma16816(float c[4], uint32_t a0, uint32_t a1,
                                         uint32_t a2, uint32_t a3,
                                         uint32_t b0, uint32_t b1){
    asm volatile(
        "mma.sync.aligned.m16n8k16.row.col.f32.bf16.bf16.f32 "
        "{%0,%1,%2,%3},{%4,%5,%6,%7},{%8,%9},{%0,%1,%2,%3};"
        : "+f"(c[0]),"+f"(c[1]),"+f"(c[2]),"+f"(c[3])
        : "r"(a0),"r"(a1),"r"(a2),"r"(a3),"r"(b0),"r"(b1));
}
#define LDMX4(r, addr) \
    asm volatile("ldmatrix.sync.aligned.m8n8.x4.shared.b16 {%0,%1,%2,%3},[%4];" \
        : "=r"((r)[0]),"=r"((r)[1]),"=r"((r)[2]),"=r"((r)[3]) : "r"(addr))

__device__ __forceinline__ void cp16(uint32_t dst, const void* src){
    asm volatile("cp.async.cg.shared.global [%0],[%1],16;" :: "r"(dst), "l"(src));
}
__device__ __forceinline__ void cp_commit(){
    asm volatile("cp.async.commit_group;" ::: "memory");
}
__device__ __forceinline__ void cp_wait(){
    asm volatile("cp.async.wait_group 0;" ::: "memory");
}
// async copy weight tile t (hi+lo) into smem buffers
__device__ __forceinline__ void copyw_async(int t, uint32_t sBhiU, uint32_t sBloU){
    const char* hi = (const char*)(g_whi + (size_t)t*128*TP);
    const char* lo = (const char*)(g_wlo + (size_t)t*128*TP);
    for (int i=threadIdx.x; i<2176; i+=256){
        cp16(sBhiU + i*16, hi + i*16);
        cp16(sBloU + i*16, lo + i*16);
    }
    cp_commit();
}

// C[128x128] += A[128x128] * B^T, bf16x3 passes, ldmatrix fragments.
// Warp tile: 32 rows x 64 cols -> acc[2][8][4].
__device__ __forceinline__ void gemm_x3(
    uint32_t aHiU, uint32_t aLoU, uint32_t bHiU, uint32_t bLoU,
    float acc[2][8][4], int mrow0, int ncol0, int lane)
{
    uint32_t offA[2], offB[4];
#pragma unroll
    for (int mt=0;mt<2;mt++)
        offA[mt] = (uint32_t)(((mrow0+16*mt+(lane&15))*TP + 8*(lane>>4))*2);
#pragma unroll
    for (int p2=0;p2<4;p2++)
        offB[p2] = (uint32_t)(((ncol0+16*p2+(lane&7)+8*((lane>>4)&1))*TP + 8*((lane>>3)&1))*2);
#pragma unroll 1
    for (int p=0;p<3;p++){
        uint32_t A = (p==2) ? aLoU : aHiU;
        uint32_t B = (p==1) ? bLoU : bHiU;
#pragma unroll 2
        for (int kt=0;kt<8;kt++){
            uint32_t koff = (uint32_t)(kt*32);
            uint32_t a[2][4];
            LDMX4(a[0], A + offA[0] + koff);
            LDMX4(a[1], A + offA[1] + koff);
#pragma unroll
            for (int p2=0;p2<4;p2++){
                uint32_t b[4];
                LDMX4(b, B + offB[p2] + koff);
                mma16816(acc[0][2*p2],   a[0][0],a[0][1],a[0][2],a[0][3], b[0],b[1]);
                mma16816(acc[1][2*p2],   a[1][0],a[1][1],a[1][2],a[1][3], b[0],b[1]);
                mma16816(acc[0][2*p2+1], a[0][0],a[0][1],a[0][2],a[0][3], b[2],b[3]);
                mma16816(acc[1][2*p2+1], a[1][0],a[1][1],a[1][2],a[1][3], b[2],b[3]);
            }
        }
    }
}

__device__ __forceinline__ void zero_acc(float acc[2][8][4]){
#pragma unroll
    for (int m=0;m<2;m++)
#pragma unroll
        for (int n=0;n<8;n++)
#pragma unroll
            for (int q=0;q<4;q++) acc[m][n][q] = 0.f;
}

// row-major fp32 [128][128] -> hi/lo tiles [r][c]
__device__ __forceinline__ void load_a_g(const float* __restrict__ src,
                                         __nv_bfloat16* sAhi, __nv_bfloat16* sAlo){
    for (int idx = threadIdx.x; idx < 16384; idx += 256){
        split_store(sAhi, sAlo, (idx>>7)*TP + (idx&127), src[idx]);
    }
}

// ---------------- K_prepw: pre-split + transpose all weight tiles -----------
__global__ __launch_bounds__(256) void k_prepw(
    const float* __restrict__ Win, const float* __restrict__ Wi,
    const float* __restrict__ Wr,  const float* __restrict__ Wo,
    const float* __restrict__ W1,  const float* __restrict__ W2)
{
    int t = blockIdx.x;
    const float* src; int ldw = 128, row0 = 0, col0 = 0;
    if (t==0) src = Win;
    else if (t==1) src = Wr;
    else if (t==2) src = Wi;
    else if (t==3) src = Wo;
    else if (t==4){ src = Wo; row0 = 128; }
    else if (t<9){ src = W1; ldw = 512; col0 = (t-5)*128; }
    else { src = W2; row0 = (t-9)*128; }
    __nv_bfloat16* hi = g_whi + (size_t)t*128*TP;
    __nv_bfloat16* lo = g_wlo + (size_t)t*128*TP;
    for (int idx = threadIdx.x; idx < 16384; idx += 256){
        int k = idx>>7, n = idx&127;
        float w = src[(size_t)(row0+k)*ldw + col0 + n];
        __nv_bfloat16 h = __float2bfloat16(w);
        hi[n*TP+k] = h;
        lo[n*TP+k] = __float2bfloat16(w - __bfloat162float(h));
    }
}

// ---------------- K0: conditioning scalars ----------------------------------
__global__ __launch_bounds__(256) void k_affine(
    const float* __restrict__ c,
    const float* __restrict__ sw1, const float* __restrict__ sb1,
    const float* __restrict__ bw1, const float* __restrict__ bb1,
    const float* __restrict__ gw1, const float* __restrict__ gb1,
    const float* __restrict__ sw2, const float* __restrict__ sb2,
    const float* __restrict__ bw2, const float* __restrict__ bb2,
    const float* __restrict__ gw2, const float* __restrict__ gb2)
{
    int warp = threadIdx.x>>5, lane = threadIdx.x&31;
    if (warp >= BSZ) return;
    const float* ws[6] = {sw1,bw1,gw1,sw2,bw2,gw2};
    const float* bs[6] = {sb1,bb1,gb1,sb2,bb2,gb2};
    for (int j=0;j<6;j++){
        float s = 0.f;
        for (int i=lane;i<128;i+=32) s += c[warp*128+i]*ws[j][i];
#pragma unroll
        for (int o=16;o>0;o>>=1) s += __shfl_down_sync(0xffffffffu, s, o);
        if (lane==0) g_scal[warp*6+j] = s + bs[j][0];
    }
}

// ---------------- K1: LN chain + u/gr/gi GEMMs + at,bt ----------------------
__global__ __launch_bounds__(256) void k1_gates(
    const float* __restrict__ x,
    const float* __restrict__ bin, const float* __restrict__ pos,
    const float* __restrict__ bi,  const float* __restrict__ br,
    const float* __restrict__ ra)
{
    extern __shared__ __align__(16) char smraw[];
    __nv_bfloat16* sAhi = (__nv_bfloat16*)smraw;
    __nv_bfloat16* sAlo = sAhi + 128*TP;
    __nv_bfloat16* sBhi = sAlo + 128*TP;
    __nv_bfloat16* sBlo = sBhi + 128*TP;
    float* sC  = (float*)(smraw + 4*TILE_B);        // u staging [128][132]
    float* sLa = (float*)(smraw + 4*TILE_B + 128*132*4);
    uint32_t sU = (uint32_t)__cvta_generic_to_shared(smraw);
    uint32_t aHiU = sU, aLoU = sU+TILE_B, bHiU = sU+2*TILE_B, bLoU = sU+3*TILE_B;
    const int tid = threadIdx.x, wid = tid>>5, lane = tid&31;
    const int t0 = blockIdx.x*128, b = t0/LQ, l0 = t0%LQ;
    const float alpha = 1.f + g_scal[b*6+0];
    const float beta  = g_scal[b*6+1];
    const int mrow0 = (wid>>1)*32, ncol0 = (wid&1)*64;
    const int group = lane>>2, tig = lane&3;

    copyw_async(0, bHiU, bLoU);                 // Win
    if (tid < 128) sLa[tid] = 8.f*logf(ra[tid]);

    // LN(x)->h->LN(h) = v -> hi/lo A tiles (warp per row)
    for (int r = wid; r < 128; r += 8){
        const float* xr = x + (size_t)(t0+r)*128;
        float v[4];
#pragma unroll
        for (int i=0;i<4;i++) v[i] = xr[lane+32*i];
        float m = warp_allred(v[0]+v[1]+v[2]+v[3]) * (1.f/128.f);
        float sq = 0.f;
#pragma unroll
        for (int i=0;i<4;i++){ v[i] -= m; sq += v[i]*v[i]; }
        float rs = rsqrtf(warp_allred(sq)*(1.f/128.f) + 1e-6f);
#pragma unroll
        for (int i=0;i<4;i++) v[i] = fmaf(alpha, v[i]*rs, beta);
        float m2 = warp_allred(v[0]+v[1]+v[2]+v[3]) * (1.f/128.f);
        float sq2 = 0.f;
#pragma unroll
        for (int i=0;i<4;i++){ v[i] -= m2; sq2 += v[i]*v[i]; }
        float rs2 = rsqrtf(warp_allred(sq2)*(1.f/128.f) + 1e-6f);
#pragma unroll
        for (int i=0;i<4;i++) split_store(sAhi, sAlo, r*TP + lane+32*i, v[i]*rs2);
    }
    cp_wait();
    __syncthreads();

    float acc[2][8][4];
    // GEMM1: u = v @ Win
    zero_acc(acc);
    gemm_x3(aHiU, aLoU, bHiU, bLoU, acc, mrow0, ncol0, lane);
    __syncthreads();
    copyw_async(1, bHiU, bLoU);                 // Wr

    // epilogue 1: u = acc + bin + pos -> sC and sA tiles
#pragma unroll
    for (int mt=0;mt<2;mt++){
        int r0 = mrow0+16*mt+group, r1 = r0+8;
#pragma unroll
        for (int nt=0;nt<8;nt++){
            int col = ncol0+8*nt+2*tig;
            float bc0 = __ldg(bin+col), bc1 = __ldg(bin+col+1);
            float2 p0 = *(const float2*)(pos + (size_t)(l0+r0)*128 + col);
            float2 p1 = *(const float2*)(pos + (size_t)(l0+r1)*128 + col);
            float u00 = acc[mt][nt][0] + bc0 + p0.x;
            float u01 = acc[mt][nt][1] + bc1 + p0.y;
            float u10 = acc[mt][nt][2] + bc0 + p1.x;
            float u11 = acc[mt][nt][3] + bc1 + p1.y;
            *(float2*)(sC + r0*132 + col) = make_float2(u00,u01);
            *(float2*)(sC + r1*132 + col) = make_float2(u10,u11);
            split_store(sAhi,sAlo, r0*TP+col,   u00);
            split_store(sAhi,sAlo, r0*TP+col+1, u01);
            split_store(sAhi,sAlo, r1*TP+col,   u10);
            split_store(sAhi,sAlo, r1*TP+col+1, u11);
        }
    }
    cp_wait();
    __syncthreads();

    // GEMM2: gr = sigmoid(u @ Wr + br); at = exp(8*gr*log a)
    zero_acc(acc);
    gemm_x3(aHiU, aLoU, bHiU, bLoU, acc, mrow0, ncol0, lane);
    __syncthreads();
    copyw_async(2, bHiU, bLoU);                 // Wi
#pragma unroll
    for (int mt=0;mt<2;mt++){
        int r0 = mrow0+16*mt+group, r1 = r0+8;
#pragma unroll
        for (int nt=0;nt<8;nt++){
            int col = ncol0+8*nt+2*tig;
            float bc0 = __ldg(br+col), bc1 = __ldg(br+col+1);
            float la0 = sLa[col], la1 = sLa[col+1];
            float a00 = __expf(sigmoidf_(acc[mt][nt][0]+bc0)*la0);
            float a01 = __expf(sigmoidf_(acc[mt][nt][1]+bc1)*la1);
            float a10 = __expf(sigmoidf_(acc[mt][nt][2]+bc0)*la0);
            float a11 = __expf(sigmoidf_(acc[mt][nt][3]+bc1)*la1);
            *(float2*)(g_at + (size_t)(t0+r0)*128 + col) = make_float2(a00,a01);
            *(float2*)(g_at + (size_t)(t0+r1)*128 + col) = make_float2(a10,a11);
            float2 u0 = *(const float2*)(sC + r0*132 + col);
            float2 u1 = *(const float2*)(sC + r1*132 + col);
            u0.x *= sqrtf(fmaxf(1.f-a00*a00,0.f));
            u0.y *= sqrtf(fmaxf(1.f-a01*a01,0.f));
            u1.x *= sqrtf(fmaxf(1.f-a10*a10,0.f));
            u1.y *= sqrtf(fmaxf(1.f-a11*a11,0.f));
            *(float2*)(sC + r0*132 + col) = u0;
            *(float2*)(sC + r1*132 + col) = u1;
        }
    }
    cp_wait();
    __syncthreads();

    // GEMM3: gi = sigmoid(u @ Wi + bi); bt = gi * sqrt(1-at^2)*u
    zero_acc(acc);
    gemm_x3(aHiU, aLoU, bHiU, bLoU, acc, mrow0, ncol0, lane);
#pragma unroll
    for (int mt=0;mt<2;mt++){
        int r0 = mrow0+16*mt+group, r1 = r0+8;
#pragma unroll
        for (int nt=0;nt<8;nt++){
            int col = ncol0+8*nt+2*tig;
            float bc0 = __ldg(bi+col), bc1 = __ldg(bi+col+1);
            float2 u0 = *(const float2*)(sC + r0*132 + col);
            float2 u1 = *(const float2*)(sC + r1*132 + col);
            float b00 = sigmoidf_(acc[mt][nt][0]+bc0)*u0.x;
            float b01 = sigmoidf_(acc[mt][nt][1]+bc1)*u0.y;
            float b10 = sigmoidf_(acc[mt][nt][2]+bc0)*u1.x;
            float b11 = sigmoidf_(acc[mt][nt][3]+bc1)*u1.y;
            *(float2*)(g_bt + (size_t)(t0+r0)*128 + col) = make_float2(b00,b01);
            *(float2*)(g_bt + (size_t)(t0+r1)*128 + col) = make_float2(b10,b11);
        }
    }
}

// ---------------- K2: chunked bidirectional scan ----------------------------
__global__ __launch_bounds__(128) void k2_reduce(){
    int b = blockIdx.x, c = blockIdx.y, d = threadIdx.x;
    size_t base = ((size_t)b*LQ + (size_t)c*CL)*128 + d;
    const float* A = g_at + base;
    const float* B = g_bt + base;
    float Af=1.f, Bf=0.f;
#pragma unroll 4
    for (int i=0;i<CL;i++){ float a=A[(size_t)i*128], bb=B[(size_t)i*128]; Bf=fmaf(a,Bf,bb); Af*=a; }
    int ci = (b*NC+c)*128+d;
    g_cfA[ci]=Af; g_cfB[ci]=Bf;
    float Ab=1.f, Bb=0.f;
#pragma unroll 4
    for (int i=CL-1;i>=0;i--){ float a=A[(size_t)i*128], bb=B[(size_t)i*128]; Bb=fmaf(a,Bb,bb); Ab*=a; }
    g_cbA[ci]=Ab; g_cbB[ci]=Bb;
}

__global__ __launch_bounds__(128) void k2_carry(){
    extern __shared__ __align__(16) char smraw[];
    float* sA = (float*)smraw; float* sB = sA + 8192;
    int b = blockIdx.x; bool fwd = (blockIdx.y == 0);
    const float* A = fwd ? g_cfA : g_cbA;
    const float* B = fwd ? g_cfB : g_cbB;
    float* car = fwd ? g_carF : g_carB;
    for (int i=threadIdx.x;i<8192;i+=128){ sA[i]=A[b*8192+i]; sB[i]=B[b*8192+i]; }
    __syncthreads();
    int d = threadIdx.x;
    float h = 0.f;
    if (fwd){
        for (int c=0;c<NC;c++){
            car[(b*NC+c)*128+d] = h;
            h = fmaf(sA[c*128+d], h, sB[c*128+d]);
        }
    } else {
        for (int c=NC-1;c>=0;c--){
            car[(b*NC+c)*128+d] = h;
            h = fmaf(sA[c*128+d], h, sB[c*128+d]);
        }
    }
}

__global__ __launch_bounds__(128) void k2_apply(){
    int b = blockIdx.x, c = blockIdx.y, d = threadIdx.x;
    size_t base = ((size_t)b*LQ + (size_t)c*CL)*128 + d;
    int ci = (b*NC+c)*128+d;
    float h = g_carF[ci];
#pragma unroll 4
    for (int i=0;i<CL;i++){
        size_t o = base + (size_t)i*128;
        h = fmaf(g_at[o], h, g_bt[o]); g_hf[o] = h;
    }
    float h2 = g_carB[ci];
#pragma unroll 4
    for (int i=CL-1;i>=0;i--){
        size_t o = base + (size_t)i*128;
        h2 = fmaf(g_at[o], h2, g_bt[o]); g_hb[o] = h2;
    }
}

// ---------------- K3: r = [hf|hb]@Wo + bo; out = x + g1*r -------------------
__global__ __launch_bounds__(256) void k3_out(
    const float* __restrict__ x, const float* __restrict__ bo,
    float* __restrict__ out)
{
    extern __shared__ __align__(16) char smraw[];
    __nv_bfloat16* sAhi = (__nv_bfloat16*)smraw;
    __nv_bfloat16* sAlo = sAhi + 128*TP;
    uint32_t sU = (uint32_t)__cvta_generic_to_shared(smraw);
    uint32_t aHiU = sU, aLoU = sU+TILE_B, bHiU = sU+2*TILE_B, bLoU = sU+3*TILE_B;
    const int tid = threadIdx.x, wid = tid>>5, lane = tid&31;
    const int t0 = blockIdx.x*128, b = t0/LQ;
    const float g1 = g_scal[b*6+2];
    const int mrow0 = (wid>>1)*32, ncol0 = (wid&1)*64;
    const int group = lane>>2, tig = lane&3;

    copyw_async(3, bHiU, bLoU);                 // Wo rows 0-127
    load_a_g(g_hf + (size_t)t0*128, sAhi, sAlo);
    cp_wait();
    __syncthreads();
    float acc[2][8][4];
    zero_acc(acc);
    gemm_x3(aHiU, aLoU, bHiU, bLoU, acc, mrow0, ncol0, lane);
    __syncthreads();
    copyw_async(4, bHiU, bLoU);                 // Wo rows 128-255
    load_a_g(g_hb + (size_t)t0*128, sAhi, sAlo);
    cp_wait();
    __syncthreads();
    gemm_x3(aHiU, aLoU, bHiU, bLoU, acc, mrow0, ncol0, lane);

#pragma unroll
    for (int mt=0;mt<2;mt++){
        int r0 = mrow0+16*mt+group, r1 = r0+8;
#pragma unroll
        for (int nt=0;nt<8;nt++){
            int col = ncol0+8*nt+2*tig;
            float bc0 = __ldg(bo+col), bc1 = __ldg(bo+col+1);
            float2 x0 = *(const float2*)(x + (size_t)(t0+r0)*128 + col);
            float2 x1 = *(const float2*)(x + (size_t)(t0+r1)*128 + col);
            float o00 = fmaf(g1, acc[mt][nt][0]+bc0, x0.x);
            float o01 = fmaf(g1, acc[mt][nt][1]+bc1, x0.y);
            float o10 = fmaf(g1, acc[mt][nt][2]+bc0, x1.x);
            float o11 = fmaf(g1, acc[mt][nt][3]+bc1, x1.y);
            *(float2*)(out + (size_t)(t0+r0)*128 + col) = make_float2(o00,o01);
            *(float2*)(out + (size_t)(t0+r1)*128 + col) = make_float2(o10,o11);
        }
    }
}

// ---------------- K4: conditioned LN + gelu MLP + gated residual ------------
__global__ __launch_bounds__(256) void k4_mlp(
    float* __restrict__ xo,
    const float* __restrict__ b1, const float* __restrict__ b2)
{
    extern __shared__ __align__(16) char smraw[];
    __nv_bfloat16* sAhi = (__nv_bfloat16*)smraw;
    __nv_bfloat16* sAlo = sAhi + 128*TP;
    __nv_bfloat16* sMhi = sAlo + 3*128*TP;      // tiles 4,5
    __nv_bfloat16* sMlo = sMhi + 128*TP;
    uint32_t sU = (uint32_t)__cvta_generic_to_shared(smraw);
    uint32_t aHiU = sU, aLoU = sU+TILE_B, bHiU = sU+2*TILE_B, bLoU = sU+3*TILE_B;
    uint32_t mHiU = sU+4*TILE_B, mLoU = sU+5*TILE_B;
    const int tid = threadIdx.x, wid = tid>>5, lane = tid&31;
    const int t0 = blockIdx.x*128, b = t0/LQ;
    const float alpha = 1.f + g_scal[b*6+3];
    const float beta  = g_scal[b*6+4];
    const float g2    = g_scal[b*6+5];
    const int mrow0 = (wid>>1)*32, ncol0 = (wid&1)*64;
    const int group = lane>>2, tig = lane&3;

    copyw_async(5, bHiU, bLoU);                 // W1 tile 0

    // conditioned LN(x2) -> sA tiles
    for (int r = wid; r < 128; r += 8){
        const float* xr = xo + (size_t)(t0+r)*128;
        float v[4];
#pragma unroll
        for (int i=0;i<4;i++) v[i] = xr[lane+32*i];
        float m = warp_allred(v[0]+v[1]+v[2]+v[3]) * (1.f/128.f);
        float sq = 0.f;
#pragma unroll
        for (int i=0;i<4;i++){ v[i] -= m; sq += v[i]*v[i]; }
        float rs = rsqrtf(warp_allred(sq)*(1.f/128.f) + 1e-6f);
#pragma unroll
        for (int i=0;i<4;i++) split_store(sAhi, sAlo, r*TP + lane+32*i, fmaf(alpha, v[i]*rs, beta));
    }

    float acc[2][8][4], oacc[2][8][4];
    zero_acc(oacc);
#pragma unroll 1
    for (int nt4=0; nt4<4; nt4++){
        cp_wait();
        __syncthreads();
        zero_acc(acc);
        gemm_x3(aHiU, aLoU, bHiU, bLoU, acc, mrow0, ncol0, lane);   // h @ W1[nt4]
        __syncthreads();
        copyw_async(9+nt4, bHiU, bLoU);         // W2 tile nt4
        // gelu -> sM tiles
#pragma unroll
        for (int mt=0;mt<2;mt++){
            int r0 = mrow0+16*mt+group, r1 = r0+8;
#pragma unroll
            for (int nt=0;nt<8;nt++){
                int col = ncol0+8*nt+2*tig;
                float bc0 = __ldg(b1+nt4*128+col), bc1 = __ldg(b1+nt4*128+col+1);
                split_store(sMhi,sMlo, r0*TP+col,   gelu_tanh(acc[mt][nt][0]+bc0));
                split_store(sMhi,sMlo, r0*TP+col+1, gelu_tanh(acc[mt][nt][1]+bc1));
                split_store(sMhi,sMlo, r1*TP+col,   gelu_tanh(acc[mt][nt][2]+bc0));
                split_store(sMhi,sMlo, r1*TP+col+1, gelu_tanh(acc[mt][nt][3]+bc1));
            }
        }
        cp_wait();
        __syncthreads();
        gemm_x3(mHiU, mLoU, bHiU, bLoU, oacc, mrow0, ncol0, lane);  // m @ W2[nt4]
        __syncthreads();
        if (nt4 < 3) copyw_async(6+nt4, bHiU, bLoU);   // W1 tile nt4+1
    }

#pragma unroll
    for (int mt=0;mt<2;mt++){
        int r0 = mrow0+16*mt+group, r1 = r0+8;
#pragma unroll
        for (int nt=0;nt<8;nt++){
            int col = ncol0+8*nt+2*tig;
            float bc0 = __ldg(b2+col), bc1 = __ldg(b2+col+1);
            float2 x0 = *(const float2*)(xo + (size_t)(t0+r0)*128 + col);
            float2 x1 = *(const float2*)(xo + (size_t)(t0+r1)*128 + col);
            float o00 = fmaf(g2, oacc[mt][nt][0]+bc0, x0.x);
            float o01 = fmaf(g2, oacc[mt][nt][1]+bc1, x0.y);
            float o10 = fmaf(g2, oacc[mt][nt][2]+bc0, x1.x);
            float o11 = fmaf(g2, oacc[mt][nt][3]+bc1, x1.y);
            *(float2*)(xo + (size_t)(t0+r0)*128 + col) = make_float2(o00,o01);
            *(float2*)(xo + (size_t)(t0+r1)*128 + col) = make_float2(o10,o11);
        }
    }
}

// ---------------- launch ----------------------------------------------------
extern "C" void kernel_launch(void* const* d_in, const int* in_sizes, int n_in,
                              void* d_out, int out_size)
{
    (void)in_sizes; (void)n_in; (void)out_size;
    const float* F[28];
    for (int i=0;i<28;i++) F[i] = (const float*)d_in[i];
    float* out = (float*)d_out;

    const int K1_SMEM = 4*TILE_B + 128*132*4 + 512;  // 207360
    const int K3_SMEM = 4*TILE_B;                    // 139264
    const int K4_SMEM = 6*TILE_B;                    // 208896
    cudaFuncSetAttribute(k1_gates, cudaFuncAttributeMaxDynamicSharedMemorySize, K1_SMEM);
    cudaFuncSetAttribute(k3_out,   cudaFuncAttributeMaxDynamicSharedMemorySize, K3_SMEM);
    cudaFuncSetAttribute(k4_mlp,   cudaFuncAttributeMaxDynamicSharedMemorySize, K4_SMEM);
    cudaFuncSetAttribute(k2_carry, cudaFuncAttributeMaxDynamicSharedMemorySize, 65536);

    k_prepw<<<13,256>>>(F[8], F[11], F[13], F[16], F[24], F[26]);
    k_affine<<<1,256>>>(F[1], F[2],F[3],F[4],F[5],F[6],F[7],
                              F[18],F[19],F[20],F[21],F[22],F[23]);
    k1_gates<<<512,256,K1_SMEM>>>(F[0], F[9], F[10], F[12], F[14], F[15]);
    dim3 gr2(BSZ, NC);
    k2_reduce<<<gr2,128>>>();
    k2_carry<<<dim3(BSZ,2),128,65536>>>();
    k2_apply<<<gr2,128>>>();
    k3_out<<<512,256,K3_SMEM>>>(F[0], F[17], out);
    k4_mlp<<<512,256,K4_SMEM>>>(out, F[25], F[27]);
}

// round 6
// speedup vs baseline: 1.7707x; 1.7707x over previous
#include <cuda_runtime.h>
#include <cuda_bf16.h>
#include <math.h>
#include <stdint.h>

#define BSZ 8
#define LQ 8192
#define NTOK (BSZ*LQ)
#define NC 64
#define CL 128
#define TP 136                      // padded tile row (bf16 elems)
#define TILE_B (128*TP*2)           // tile bytes = 34816
#define NTHR 512

// ---------------- scratch (device globals; no allocations allowed) ----------
__device__ float g_at[(size_t)NTOK*128];
__device__ float g_bt[(size_t)NTOK*128];
__device__ float g_cfA[BSZ*NC*128], g_cfB[BSZ*NC*128];
__device__ float g_cbA[BSZ*NC*128], g_cbB[BSZ*NC*128];
__device__ float g_carF[BSZ*NC*128], g_carB[BSZ*NC*128];
__device__ float g_scal[BSZ*6];
// pre-split transposed weight tiles: 13 tiles of [128][TP] bf16, hi and lo
__device__ __align__(16) __nv_bfloat16 g_whi[13*128*TP];
__device__ __align__(16) __nv_bfloat16 g_wlo[13*128*TP];

// ---------------- helpers ---------------------------------------------------
__device__ __forceinline__ float warp_allred(float v){
#pragma unroll
    for (int o=16;o>0;o>>=1) v += __shfl_xor_sync(0xffffffffu, v, o);
    return v;
}
__device__ __forceinline__ float sigmoidf_(float z){
    return __fdividef(1.f, 1.f + __expf(-z));
}
__device__ __forceinline__ float gelu_tanh(float v){
    float t;
    asm("tanh.approx.f32 %0, %1;" : "=f"(t) : "f"(0.7978845608028654f * fmaf(0.044715f*v, v*v, v)));
    return 0.5f*v*(1.f+t);
}
__device__ __forceinline__ void split_store(__nv_bfloat16* hi, __nv_bfloat16* lo,
                                            int off, float v){
    __nv_bfloat16 h = __float2bfloat16(v);
    hi[off] = h;
    lo[off] = __float2bfloat16(v - __bfloat162float(h));
}

// mma.sync m16n8k16 bf16 -> f32
__device__ __forceinline__ void mma16816(float c[4], uint32_t a0, uint32_t a1,
                                         uint32_t a2, uint32_t a3,
                                         uint32_t b0, uint32_t b1){
    asm volatile(
        "mma.sync.aligned.m16n8k16.row.col.f32.bf16.bf16.f32 "
        "{%0,%1,%2,%3},{%4,%5,%6,%7},{%8,%9},{%0,%1,%2,%3};"
        : "+f"(c[0]),"+f"(c[1]),"+f"(c[2]),"+f"(c[3])
        : "r"(a0),"r"(a1),"r"(a2),"r"(a3),"r"(b0),"r"(b1));
}
#define LDMX4(r, addr) \
    asm volatile("ldmatrix.sync.aligned.m8n8.x4.shared.b16 {%0,%1,%2,%3},[%4];" \
        : "=r"((r)[0]),"=r"((r)[1]),"=r"((r)[2]),"=r"((r)[3]) : "r"(addr))

__device__ __forceinline__ void cp16(uint32_t dst, const void* src){
    asm volatile("cp.async.cg.shared.global [%0],[%1],16;" :: "r"(dst), "l"(src));
}
__device__ __forceinline__ void cp_commit(){
    asm volatile("cp.async.commit_group;" ::: "memory");
}
__device__ __forceinline__ void cp_wait(){
    asm volatile("cp.async.wait_group 0;" ::: "memory");
}
// async copy weight tile t (hi+lo) into smem buffers
__device__ __forceinline__ void copyw_async(int t, uint32_t sBhiU, uint32_t sBloU){
    const char* hi = (const char*)(g_whi + (size_t)t*128*TP);
    const char* lo = (const char*)(g_wlo + (size_t)t*128*TP);
    for (int i=threadIdx.x; i<2176; i+=NTHR){
        cp16(sBhiU + i*16, hi + i*16);
        cp16(sBloU + i*16, lo + i*16);
    }
    cp_commit();
}

// C[16x64 warp tile] += A * B^T, bf16x3 passes, ldmatrix fragments.
__device__ __forceinline__ void gemm_x3(
    uint32_t aHiU, uint32_t aLoU, uint32_t bHiU, uint32_t bLoU,
    float acc[8][4], int mrow0, int ncol0, int lane)
{
    uint32_t offA = (uint32_t)(((mrow0 + (lane&15))*TP + 8*(lane>>4))*2);
    uint32_t offB[4];
#pragma unroll
    for (int p2=0;p2<4;p2++)
        offB[p2] = (uint32_t)(((ncol0+16*p2+(lane&7)+8*((lane>>4)&1))*TP + 8*((lane>>3)&1))*2);
#pragma unroll 1
    for (int p=0;p<3;p++){
        uint32_t A = (p==2) ? aLoU : aHiU;
        uint32_t B = (p==1) ? bLoU : bHiU;
#pragma unroll 2
        for (int kt=0;kt<8;kt++){
            uint32_t koff = (uint32_t)(kt*32);
            uint32_t a[4];
            LDMX4(a, A + offA + koff);
#pragma unroll
            for (int p2=0;p2<4;p2++){
                uint32_t b[4];
                LDMX4(b, B + offB[p2] + koff);
                mma16816(acc[2*p2],   a[0],a[1],a[2],a[3], b[0],b[1]);
                mma16816(acc[2*p2+1], a[0],a[1],a[2],a[3], b[2],b[3]);
            }
        }
    }
}

__device__ __forceinline__ void zero_acc(float acc[8][4]){
#pragma unroll
    for (int n=0;n<8;n++)
#pragma unroll
        for (int q=0;q<4;q++) acc[n][q] = 0.f;
}

// ---------------- K_prepw: pre-split + transpose all weight tiles -----------
__global__ __launch_bounds__(256) void k_prepw(
    const float* __restrict__ Win, const float* __restrict__ Wi,
    const float* __restrict__ Wr,  const float* __restrict__ Wo,
    const float* __restrict__ W1,  const float* __restrict__ W2)
{
    int t = blockIdx.x;
    const float* src; int ldw = 128, row0 = 0, col0 = 0;
    if (t==0) src = Win;
    else if (t==1) src = Wr;
    else if (t==2) src = Wi;
    else if (t==3) src = Wo;
    else if (t==4){ src = Wo; row0 = 128; }
    else if (t<9){ src = W1; ldw = 512; col0 = (t-5)*128; }
    else { src = W2; row0 = (t-9)*128; }
    __nv_bfloat16* hi = g_whi + (size_t)t*128*TP;
    __nv_bfloat16* lo = g_wlo + (size_t)t*128*TP;
    for (int idx = threadIdx.x; idx < 16384; idx += 256){
        int k = idx>>7, n = idx&127;
        float w = src[(size_t)(row0+k)*ldw + col0 + n];
        __nv_bfloat16 h = __float2bfloat16(w);
        hi[n*TP+k] = h;
        lo[n*TP+k] = __float2bfloat16(w - __bfloat162float(h));
    }
}

// ---------------- K0: conditioning scalars ----------------------------------
__global__ __launch_bounds__(256) void k_affine(
    const float* __restrict__ c,
    const float* __restrict__ sw1, const float* __restrict__ sb1,
    const float* __restrict__ bw1, const float* __restrict__ bb1,
    const float* __restrict__ gw1, const float* __restrict__ gb1,
    const float* __restrict__ sw2, const float* __restrict__ sb2,
    const float* __restrict__ bw2, const float* __restrict__ bb2,
    const float* __restrict__ gw2, const float* __restrict__ gb2)
{
    int warp = threadIdx.x>>5, lane = threadIdx.x&31;
    if (warp >= BSZ) return;
    const float* ws[6] = {sw1,bw1,gw1,sw2,bw2,gw2};
    const float* bs[6] = {sb1,bb1,gb1,sb2,bb2,gb2};
    for (int j=0;j<6;j++){
        float s = 0.f;
        for (int i=lane;i<128;i+=32) s += c[warp*128+i]*ws[j][i];
#pragma unroll
        for (int o=16;o>0;o>>=1) s += __shfl_down_sync(0xffffffffu, s, o);
        if (lane==0) g_scal[warp*6+j] = s + bs[j][0];
    }
}

// ---------------- K1: LN chain + u/gr/gi GEMMs + at,bt + chunk reduce -------
__global__ __launch_bounds__(NTHR) void k1_gates(
    const float* __restrict__ x,
    const float* __restrict__ bin, const float* __restrict__ pos,
    const float* __restrict__ bi,  const float* __restrict__ br,
    const float* __restrict__ ra)
{
    extern __shared__ __align__(16) char smraw[];
    __nv_bfloat16* sAhi = (__nv_bfloat16*)smraw;
    __nv_bfloat16* sAlo = sAhi + 128*TP;
    float* sC  = (float*)(smraw + 4*TILE_B);        // u staging [128][132]
    float* sLa = (float*)(smraw + 4*TILE_B + 128*132*4);
    uint32_t sU = (uint32_t)__cvta_generic_to_shared(smraw);
    uint32_t aHiU = sU, aLoU = sU+TILE_B, bHiU = sU+2*TILE_B, bLoU = sU+3*TILE_B;
    const int tid = threadIdx.x, wid = tid>>5, lane = tid&31;
    const int t0 = blockIdx.x*128, b = t0/LQ, l0 = t0%LQ;
    const float alpha = 1.f + g_scal[b*6+0];
    const float beta  = g_scal[b*6+1];
    const int mrow0 = (wid>>1)*16, ncol0 = (wid&1)*64;
    const int group = lane>>2, tig = lane&3;

    copyw_async(0, bHiU, bLoU);                 // Win
    if (tid < 128) sLa[tid] = 8.f*logf(ra[tid]);

    // LN(x)->h->LN(h) = v -> hi/lo A tiles (warp per row)
    for (int r = wid; r < 128; r += 16){
        const float* xr = x + (size_t)(t0+r)*128;
        float v[4];
#pragma unroll
        for (int i=0;i<4;i++) v[i] = xr[lane+32*i];
        float m = warp_allred(v[0]+v[1]+v[2]+v[3]) * (1.f/128.f);
        float sq = 0.f;
#pragma unroll
        for (int i=0;i<4;i++){ v[i] -= m; sq += v[i]*v[i]; }
        float rs = rsqrtf(warp_allred(sq)*(1.f/128.f) + 1e-6f);
#pragma unroll
        for (int i=0;i<4;i++) v[i] = fmaf(alpha, v[i]*rs, beta);
        float m2 = warp_allred(v[0]+v[1]+v[2]+v[3]) * (1.f/128.f);
        float sq2 = 0.f;
#pragma unroll
        for (int i=0;i<4;i++){ v[i] -= m2; sq2 += v[i]*v[i]; }
        float rs2 = rsqrtf(warp_allred(sq2)*(1.f/128.f) + 1e-6f);
#pragma unroll
        for (int i=0;i<4;i++) split_store(sAhi, sAlo, r*TP + lane+32*i, v[i]*rs2);
    }
    cp_wait();
    __syncthreads();

    float acc[8][4];
    // GEMM1: u = v @ Win
    zero_acc(acc);
    gemm_x3(aHiU, aLoU, bHiU, bLoU, acc, mrow0, ncol0, lane);
    __syncthreads();
    copyw_async(1, bHiU, bLoU);                 // Wr

    // epilogue 1: u = acc + bin + pos -> sC and sA tiles
    {
        int r0 = mrow0+group, r1 = r0+8;
#pragma unroll
        for (int nt=0;nt<8;nt++){
            int col = ncol0+8*nt+2*tig;
            float bc0 = __ldg(bin+col), bc1 = __ldg(bin+col+1);
            float2 p0 = *(const float2*)(pos + (size_t)(l0+r0)*128 + col);
            float2 p1 = *(const float2*)(pos + (size_t)(l0+r1)*128 + col);
            float u00 = acc[nt][0] + bc0 + p0.x;
            float u01 = acc[nt][1] + bc1 + p0.y;
            float u10 = acc[nt][2] + bc0 + p1.x;
            float u11 = acc[nt][3] + bc1 + p1.y;
            *(float2*)(sC + r0*132 + col) = make_float2(u00,u01);
            *(float2*)(sC + r1*132 + col) = make_float2(u10,u11);
            split_store(sAhi,sAlo, r0*TP+col,   u00);
            split_store(sAhi,sAlo, r0*TP+col+1, u01);
            split_store(sAhi,sAlo, r1*TP+col,   u10);
            split_store(sAhi,sAlo, r1*TP+col+1, u11);
        }
    }
    cp_wait();
    __syncthreads();

    // GEMM2: gr = sigmoid(u @ Wr + br); at = exp(8*gr*log a)
    zero_acc(acc);
    gemm_x3(aHiU, aLoU, bHiU, bLoU, acc, mrow0, ncol0, lane);
    __syncthreads();
    copyw_async(2, bHiU, bLoU);                 // Wi
    {
        int r0 = mrow0+group, r1 = r0+8;
#pragma unroll
        for (int nt=0;nt<8;nt++){
            int col = ncol0+8*nt+2*tig;
            float bc0 = __ldg(br+col), bc1 = __ldg(br+col+1);
            float la0 = sLa[col], la1 = sLa[col+1];
            float a00 = __expf(sigmoidf_(acc[nt][0]+bc0)*la0);
            float a01 = __expf(sigmoidf_(acc[nt][1]+bc1)*la1);
            float a10 = __expf(sigmoidf_(acc[nt][2]+bc0)*la0);
            float a11 = __expf(sigmoidf_(acc[nt][3]+bc1)*la1);
            *(float2*)(g_at + (size_t)(t0+r0)*128 + col) = make_float2(a00,a01);
            *(float2*)(g_at + (size_t)(t0+r1)*128 + col) = make_float2(a10,a11);
            float2 u0 = *(const float2*)(sC + r0*132 + col);
            float2 u1 = *(const float2*)(sC + r1*132 + col);
            u0.x *= sqrtf(fmaxf(1.f-a00*a00,0.f));
            u0.y *= sqrtf(fmaxf(1.f-a01*a01,0.f));
            u1.x *= sqrtf(fmaxf(1.f-a10*a10,0.f));
            u1.y *= sqrtf(fmaxf(1.f-a11*a11,0.f));
            *(float2*)(sC + r0*132 + col) = u0;
            *(float2*)(sC + r1*132 + col) = u1;
        }
    }
    cp_wait();
    __syncthreads();

    // GEMM3: gi = sigmoid(u @ Wi + bi); bt = gi * sqrt(1-at^2)*u
    zero_acc(acc);
    gemm_x3(aHiU, aLoU, bHiU, bLoU, acc, mrow0, ncol0, lane);
    {
        int r0 = mrow0+group, r1 = r0+8;
#pragma unroll
        for (int nt=0;nt<8;nt++){
            int col = ncol0+8*nt+2*tig;
            float bc0 = __ldg(bi+col), bc1 = __ldg(bi+col+1);
            float2 u0 = *(const float2*)(sC + r0*132 + col);
            float2 u1 = *(const float2*)(sC + r1*132 + col);
            float b00 = sigmoidf_(acc[nt][0]+bc0)*u0.x;
            float b01 = sigmoidf_(acc[nt][1]+bc1)*u0.y;
            float b10 = sigmoidf_(acc[nt][2]+bc0)*u1.x;
            float b11 = sigmoidf_(acc[nt][3]+bc1)*u1.y;
            *(float2*)(g_bt + (size_t)(t0+r0)*128 + col) = make_float2(b00,b01);
            *(float2*)(g_bt + (size_t)(t0+r1)*128 + col) = make_float2(b10,b11);
        }
    }
    __syncthreads();   // make at/bt visible block-wide

    // fused chunk reduce (this block's 128 tokens == scan chunk)
    if (tid < 256){
        const int d = tid & 127;
        const int chunk = (t0 % LQ) / CL;
        const int ci = (b*NC + chunk)*128 + d;
        const float* A = g_at + (size_t)t0*128 + d;
        const float* Bv = g_bt + (size_t)t0*128 + d;
        if (tid < 128){
            float Af=1.f, Bf=0.f;
#pragma unroll 8
            for (int i=0;i<CL;i++){
                float a=A[(size_t)i*128], bb=Bv[(size_t)i*128];
                Bf=fmaf(a,Bf,bb); Af*=a;
            }
            g_cfA[ci]=Af; g_cfB[ci]=Bf;
        } else {
            float Ab=1.f, Bb=0.f;
#pragma unroll 8
            for (int i=CL-1;i>=0;i--){
                float a=A[(size_t)i*128], bb=Bv[(size_t)i*128];
                Bb=fmaf(a,Bb,bb); Ab*=a;
            }
            g_cbA[ci]=Ab; g_cbB[ci]=Bb;
        }
    }
}

// ---------------- K2: inter-chunk carry scan --------------------------------
__global__ __launch_bounds__(128) void k2_carry(){
    extern __shared__ __align__(16) char smraw[];
    float* sA = (float*)smraw; float* sB = sA + 8192;
    int b = blockIdx.x; bool fwd = (blockIdx.y == 0);
    const float* A = fwd ? g_cfA : g_cbA;
    const float* B = fwd ? g_cfB : g_cbB;
    float* car = fwd ? g_carF : g_carB;
    for (int i=threadIdx.x;i<8192;i+=128){ sA[i]=A[b*8192+i]; sB[i]=B[b*8192+i]; }
    __syncthreads();
    int d = threadIdx.x;
    float h = 0.f;
    if (fwd){
        for (int c=0;c<NC;c++){
            car[(b*NC+c)*128+d] = h;
            h = fmaf(sA[c*128+d], h, sB[c*128+d]);
        }
    } else {
        for (int c=NC-1;c>=0;c--){
            car[(b*NC+c)*128+d] = h;
            h = fmaf(sA[c*128+d], h, sB[c*128+d]);
        }
    }
}

// ---------------- K3: apply scan + r = [hf|hb]@Wo + bo; out = x + g1*r ------
__global__ __launch_bounds__(NTHR) void k3_out(
    const float* __restrict__ x, const float* __restrict__ bo,
    float* __restrict__ out)
{
    extern __shared__ __align__(16) char smraw[];
    __nv_bfloat16* sFhi = (__nv_bfloat16*)smraw;          // hf tiles
    __nv_bfloat16* sFlo = sFhi + 128*TP;
    __nv_bfloat16* sHhi = sFlo + 128*TP;                  // hb tiles
    __nv_bfloat16* sHlo = sHhi + 128*TP;
    uint32_t sU = (uint32_t)__cvta_generic_to_shared(smraw);
    uint32_t fHiU = sU, fLoU = sU+TILE_B;
    uint32_t hHiU = sU+2*TILE_B, hLoU = sU+3*TILE_B;
    uint32_t bHiU = sU+4*TILE_B, bLoU = sU+5*TILE_B;
    const int tid = threadIdx.x, wid = tid>>5, lane = tid&31;
    const int t0 = blockIdx.x*128, b = t0/LQ;
    const float g1 = g_scal[b*6+2];
    const int mrow0 = (wid>>1)*16, ncol0 = (wid&1)*64;
    const int group = lane>>2, tig = lane&3;

    copyw_async(3, bHiU, bLoU);                 // Wo rows 0-127

    // fused apply scan: stream at/bt from global, write hf/hb into bf16 tiles
    if (tid < 256){
        const int d = tid & 127;
        const int chunk = (t0 % LQ) / CL;
        const int ci = (b*NC + chunk)*128 + d;
        const float* A = g_at + (size_t)t0*128 + d;
        const float* Bv = g_bt + (size_t)t0*128 + d;
        if (tid < 128){
            float h = g_carF[ci];
#pragma unroll 4
            for (int i=0;i<CL;i++){
                h = fmaf(A[(size_t)i*128], h, Bv[(size_t)i*128]);
                split_store(sFhi, sFlo, i*TP + d, h);
            }
        } else {
            float h = g_carB[ci];
#pragma unroll 4
            for (int i=CL-1;i>=0;i--){
                h = fmaf(A[(size_t)i*128], h, Bv[(size_t)i*128]);
                split_store(sHhi, sHlo, i*TP + d, h);
            }
        }
    }
    cp_wait();
    __syncthreads();

    float acc[8][4];
    zero_acc(acc);
    gemm_x3(fHiU, fLoU, bHiU, bLoU, acc, mrow0, ncol0, lane);
    __syncthreads();
    copyw_async(4, bHiU, bLoU);                 // Wo rows 128-255
    cp_wait();
    __syncthreads();
    gemm_x3(hHiU, hLoU, bHiU, bLoU, acc, mrow0, ncol0, lane);

    {
        int r0 = mrow0+group, r1 = r0+8;
#pragma unroll
        for (int nt=0;nt<8;nt++){
            int col = ncol0+8*nt+2*tig;
            float bc0 = __ldg(bo+col), bc1 = __ldg(bo+col+1);
            float2 x0 = *(const float2*)(x + (size_t)(t0+r0)*128 + col);
            float2 x1 = *(const float2*)(x + (size_t)(t0+r1)*128 + col);
            float o00 = fmaf(g1, acc[nt][0]+bc0, x0.x);
            float o01 = fmaf(g1, acc[nt][1]+bc1, x0.y);
            float o10 = fmaf(g1, acc[nt][2]+bc0, x1.x);
            float o11 = fmaf(g1, acc[nt][3]+bc1, x1.y);
            *(float2*)(out + (size_t)(t0+r0)*128 + col) = make_float2(o00,o01);
            *(float2*)(out + (size_t)(t0+r1)*128 + col) = make_float2(o10,o11);
        }
    }
}

// ---------------- K4: conditioned LN + gelu MLP + gated residual ------------
__global__ __launch_bounds__(NTHR) void k4_mlp(
    float* __restrict__ xo,
    const float* __restrict__ b1, const float* __restrict__ b2)
{
    extern __shared__ __align__(16) char smraw[];
    __nv_bfloat16* sAhi = (__nv_bfloat16*)smraw;
    __nv_bfloat16* sAlo = sAhi + 128*TP;
    __nv_bfloat16* sMhi = sAlo + 3*128*TP;      // tiles 4,5
    __nv_bfloat16* sMlo = sMhi + 128*TP;
    uint32_t sU = (uint32_t)__cvta_generic_to_shared(smraw);
    uint32_t aHiU = sU, aLoU = sU+TILE_B, bHiU = sU+2*TILE_B, bLoU = sU+3*TILE_B;
    uint32_t mHiU = sU+4*TILE_B, mLoU = sU+5*TILE_B;
    const int tid = threadIdx.x, wid = tid>>5, lane = tid&31;
    const int t0 = blockIdx.x*128, b = t0/LQ;
    const float alpha = 1.f + g_scal[b*6+3];
    const float beta  = g_scal[b*6+4];
    const float g2    = g_scal[b*6+5];
    const int mrow0 = (wid>>1)*16, ncol0 = (wid&1)*64;
    const int group = lane>>2, tig = lane&3;

    copyw_async(5, bHiU, bLoU);                 // W1 tile 0

    // conditioned LN(x2) -> sA tiles
    for (int r = wid; r < 128; r += 16){
        const float* xr = xo + (size_t)(t0+r)*128;
        float v[4];
#pragma unroll
        for (int i=0;i<4;i++) v[i] = xr[lane+32*i];
        float m = warp_allred(v[0]+v[1]+v[2]+v[3]) * (1.f/128.f);
        float sq = 0.f;
#pragma unroll
        for (int i=0;i<4;i++){ v[i] -= m; sq += v[i]*v[i]; }
        float rs = rsqrtf(warp_allred(sq)*(1.f/128.f) + 1e-6f);
#pragma unroll
        for (int i=0;i<4;i++) split_store(sAhi, sAlo, r*TP + lane+32*i, fmaf(alpha, v[i]*rs, beta));
    }

    float acc[8][4], oacc[8][4];
    zero_acc(oacc);
#pragma unroll 1
    for (int nt4=0; nt4<4; nt4++){
        cp_wait();
        __syncthreads();
        zero_acc(acc);
        gemm_x3(aHiU, aLoU, bHiU, bLoU, acc, mrow0, ncol0, lane);   // h @ W1[nt4]
        __syncthreads();
        copyw_async(9+nt4, bHiU, bLoU);         // W2 tile nt4
        // gelu -> sM tiles
        {
            int r0 = mrow0+group, r1 = r0+8;
#pragma unroll
            for (int nt=0;nt<8;nt++){
                int col = ncol0+8*nt+2*tig;
                float bc0 = __ldg(b1+nt4*128+col), bc1 = __ldg(b1+nt4*128+col+1);
                split_store(sMhi,sMlo, r0*TP+col,   gelu_tanh(acc[nt][0]+bc0));
                split_store(sMhi,sMlo, r0*TP+col+1, gelu_tanh(acc[nt][1]+bc1));
                split_store(sMhi,sMlo, r1*TP+col,   gelu_tanh(acc[nt][2]+bc0));
                split_store(sMhi,sMlo, r1*TP+col+1, gelu_tanh(acc[nt][3]+bc1));
            }
        }
        cp_wait();
        __syncthreads();
        gemm_x3(mHiU, mLoU, bHiU, bLoU, oacc, mrow0, ncol0, lane);  // m @ W2[nt4]
        __syncthreads();
        if (nt4 < 3) copyw_async(6+nt4, bHiU, bLoU);   // W1 tile nt4+1
    }

    {
        int r0 = mrow0+group, r1 = r0+8;
#pragma unroll
        for (int nt=0;nt<8;nt++){
            int col = ncol0+8*nt+2*tig;
            float bc0 = __ldg(b2+col), bc1 = __ldg(b2+col+1);
            float2 x0 = *(const float2*)(xo + (size_t)(t0+r0)*128 + col);
            float2 x1 = *(const float2*)(xo + (size_t)(t0+r1)*128 + col);
            float o00 = fmaf(g2, oacc[nt][0]+bc0, x0.x);
            float o01 = fmaf(g2, oacc[nt][1]+bc1, x0.y);
            float o10 = fmaf(g2, oacc[nt][2]+bc0, x1.x);
            float o11 = fmaf(g2, oacc[nt][3]+bc1, x1.y);
            *(float2*)(xo + (size_t)(t0+r0)*128 + col) = make_float2(o00,o01);
            *(float2*)(xo + (size_t)(t0+r1)*128 + col) = make_float2(o10,o11);
        }
    }
}

// ---------------- launch ----------------------------------------------------
extern "C" void kernel_launch(void* const* d_in, const int* in_sizes, int n_in,
                              void* d_out, int out_size)
{
    (void)in_sizes; (void)n_in; (void)out_size;
    const float* F[28];
    for (int i=0;i<28;i++) F[i] = (const float*)d_in[i];
    float* out = (float*)d_out;

    const int K1_SMEM = 4*TILE_B + 128*132*4 + 512;  // 207360
    const int K3_SMEM = 6*TILE_B;                    // 208896
    const int K4_SMEM = 6*TILE_B;                    // 208896
    cudaFuncSetAttribute(k1_gates, cudaFuncAttributeMaxDynamicSharedMemorySize, K1_SMEM);
    cudaFuncSetAttribute(k3_out,   cudaFuncAttributeMaxDynamicSharedMemorySize, K3_SMEM);
    cudaFuncSetAttribute(k4_mlp,   cudaFuncAttributeMaxDynamicSharedMemorySize, K4_SMEM);
    cudaFuncSetAttribute(k2_carry, cudaFuncAttributeMaxDynamicSharedMemorySize, 65536);

    k_prepw<<<13,256>>>(F[8], F[11], F[13], F[16], F[24], F[26]);
    k_affine<<<1,256>>>(F[1], F[2],F[3],F[4],F[5],F[6],F[7],
                              F[18],F[19],F[20],F[21],F[22],F[23]);
    k1_gates<<<512,NTHR,K1_SMEM>>>(F[0], F[9], F[10], F[12], F[14], F[15]);
    k2_carry<<<dim3(BSZ,2),128,65536>>>();
    k3_out<<<512,NTHR,K3_SMEM>>>(F[0], F[17], out);
    k4_mlp<<<512,NTHR,K4_SMEM>>>(out, F[25], F[27]);
}

// round 7
// speedup vs baseline: 1.8490x; 1.0443x over previous
#include <cuda_runtime.h>
#include <cuda_bf16.h>
#include <math.h>
#include <stdint.h>

#define BSZ 8
#define LQ 8192
#define NTOK (BSZ*LQ)
#define NC 64
#define CL 128
#define TP 136                      // padded tile row (bf16 elems)
#define TILE_B (128*TP*2)           // tile bytes = 34816
#define NTHR 512

// ---------------- scratch (device globals; no allocations allowed) ----------
__device__ float g_at[(size_t)NTOK*128];
__device__ float g_bt[(size_t)NTOK*128];
__device__ float g_cfA[BSZ*NC*128], g_cfB[BSZ*NC*128];
__device__ float g_cbA[BSZ*NC*128], g_cbB[BSZ*NC*128];
__device__ float g_carF[BSZ*NC*128], g_carB[BSZ*NC*128];
__device__ float g_scal[BSZ*6];
// pre-split transposed weight tiles: 13 tiles of [128][TP] bf16, hi and lo
__device__ __align__(16) __nv_bfloat16 g_whi[13*128*TP];
__device__ __align__(16) __nv_bfloat16 g_wlo[13*128*TP];

// ---------------- helpers ---------------------------------------------------
__device__ __forceinline__ float warp_allred(float v){
#pragma unroll
    for (int o=16;o>0;o>>=1) v += __shfl_xor_sync(0xffffffffu, v, o);
    return v;
}
__device__ __forceinline__ float sigmoidf_(float z){
    return __fdividef(1.f, 1.f + __expf(-z));
}
__device__ __forceinline__ float gelu_tanh(float v){
    float t;
    asm("tanh.approx.f32 %0, %1;" : "=f"(t) : "f"(0.7978845608028654f * fmaf(0.044715f*v, v*v, v)));
    return 0.5f*v*(1.f+t);
}
__device__ __forceinline__ void split_store(__nv_bfloat16* hi, __nv_bfloat16* lo,
                                            int off, float v){
    __nv_bfloat16 h = __float2bfloat16(v);
    hi[off] = h;
    lo[off] = __float2bfloat16(v - __bfloat162float(h));
}

// mma.sync m16n8k16 bf16 -> f32
__device__ __forceinline__ void mma16816(float c[4], uint32_t a0, uint32_t a1,
                                         uint32_t a2, uint32_t a3,
                                         uint32_t b0, uint32_t b1){
    asm volatile(
        "mma.sync.aligned.m16n8k16.row.col.f32.bf16.bf16.f32 "
        "{%0,%1,%2,%3},{%4,%5,%6,%7},{%8,%9},{%0,%1,%2,%3};"
        : "+f"(c[0]),"+f"(c[1]),"+f"(c[2]),"+f"(c[3])
        : "r"(a0),"r"(a1),"r"(a2),"r"(a3),"r"(b0),"r"(b1));
}
#define LDMX4(r, addr) \
    asm volatile("ldmatrix.sync.aligned.m8n8.x4.shared.b16 {%0,%1,%2,%3},[%4];" \
        : "=r"((r)[0]),"=r"((r)[1]),"=r"((r)[2]),"=r"((r)[3]) : "r"(addr))

__device__ __forceinline__ void cp16(uint32_t dst, const void* src){
    asm volatile("cp.async.cg.shared.global [%0],[%1],16;" :: "r"(dst), "l"(src));
}
__device__ __forceinline__ void cp_commit(){
    asm volatile("cp.async.commit_group;" ::: "memory");
}
__device__ __forceinline__ void cp_wait(){
    asm volatile("cp.async.wait_group 0;" ::: "memory");
}
// async copy weight tile t (hi+lo) into smem buffers
__device__ __forceinline__ void copyw_async(int t, uint32_t sBhiU, uint32_t sBloU){
    const char* hi = (const char*)(g_whi + (size_t)t*128*TP);
    const char* lo = (const char*)(g_wlo + (size_t)t*128*TP);
    for (int i=threadIdx.x; i<2176; i+=NTHR){
        cp16(sBhiU + i*16, hi + i*16);
        cp16(sBloU + i*16, lo + i*16);
    }
    cp_commit();
}

// C[16x64 warp tile] += A * B^T, bf16x3 passes, ldmatrix fragments.
__device__ __forceinline__ void gemm_x3(
    uint32_t aHiU, uint32_t aLoU, uint32_t bHiU, uint32_t bLoU,
    float acc[8][4], int mrow0, int ncol0, int lane)
{
    uint32_t offA = (uint32_t)(((mrow0 + (lane&15))*TP + 8*(lane>>4))*2);
    uint32_t offB[4];
#pragma unroll
    for (int p2=0;p2<4;p2++)
        offB[p2] = (uint32_t)(((ncol0+16*p2+(lane&7)+8*((lane>>4)&1))*TP + 8*((lane>>3)&1))*2);
#pragma unroll 1
    for (int p=0;p<3;p++){
        uint32_t A = (p==2) ? aLoU : aHiU;
        uint32_t B = (p==1) ? bLoU : bHiU;
#pragma unroll 2
        for (int kt=0;kt<8;kt++){
            uint32_t koff = (uint32_t)(kt*32);
            uint32_t a[4];
            LDMX4(a, A + offA + koff);
#pragma unroll
            for (int p2=0;p2<4;p2++){
                uint32_t b[4];
                LDMX4(b, B + offB[p2] + koff);
                mma16816(acc[2*p2],   a[0],a[1],a[2],a[3], b[0],b[1]);
                mma16816(acc[2*p2+1], a[0],a[1],a[2],a[3], b[2],b[3]);
            }
        }
    }
}

__device__ __forceinline__ void zero_acc(float acc[8][4]){
#pragma unroll
    for (int n=0;n<8;n++)
#pragma unroll
        for (int q=0;q<4;q++) acc[n][q] = 0.f;
}

// ---------------- K_prepw: pre-split + transpose all weight tiles -----------
__global__ __launch_bounds__(256) void k_prepw(
    const float* __restrict__ Win, const float* __restrict__ Wi,
    const float* __restrict__ Wr,  const float* __restrict__ Wo,
    const float* __restrict__ W1,  const float* __restrict__ W2)
{
    int t = blockIdx.x;
    const float* src; int ldw = 128, row0 = 0, col0 = 0;
    if (t==0) src = Win;
    else if (t==1) src = Wr;
    else if (t==2) src = Wi;
    else if (t==3) src = Wo;
    else if (t==4){ src = Wo; row0 = 128; }
    else if (t<9){ src = W1; ldw = 512; col0 = (t-5)*128; }
    else { src = W2; row0 = (t-9)*128; }
    __nv_bfloat16* hi = g_whi + (size_t)t*128*TP;
    __nv_bfloat16* lo = g_wlo + (size_t)t*128*TP;
    for (int idx = threadIdx.x; idx < 16384; idx += 256){
        int k = idx>>7, n = idx&127;
        float w = src[(size_t)(row0+k)*ldw + col0 + n];
        __nv_bfloat16 h = __float2bfloat16(w);
        hi[n*TP+k] = h;
        lo[n*TP+k] = __float2bfloat16(w - __bfloat162float(h));
    }
}

// ---------------- K0: conditioning scalars ----------------------------------
__global__ __launch_bounds__(256) void k_affine(
    const float* __restrict__ c,
    const float* __restrict__ sw1, const float* __restrict__ sb1,
    const float* __restrict__ bw1, const float* __restrict__ bb1,
    const float* __restrict__ gw1, const float* __restrict__ gb1,
    const float* __restrict__ sw2, const float* __restrict__ sb2,
    const float* __restrict__ bw2, const float* __restrict__ bb2,
    const float* __restrict__ gw2, const float* __restrict__ gb2)
{
    int warp = threadIdx.x>>5, lane = threadIdx.x&31;
    if (warp >= BSZ) return;
    const float* ws[6] = {sw1,bw1,gw1,sw2,bw2,gw2};
    const float* bs[6] = {sb1,bb1,gb1,sb2,bb2,gb2};
    for (int j=0;j<6;j++){
        float s = 0.f;
        for (int i=lane;i<128;i+=32) s += c[warp*128+i]*ws[j][i];
#pragma unroll
        for (int o=16;o>0;o>>=1) s += __shfl_down_sync(0xffffffffu, s, o);
        if (lane==0) g_scal[warp*6+j] = s + bs[j][0];
    }
}

// ---------------- K_nop: launch-order pad so ncu's 4th launch is k1 ---------
__global__ void k_nop(){}

// ---------------- K1: LN chain + u/gr/gi GEMMs + at,bt + chunk reduce -------
__global__ __launch_bounds__(NTHR) void k1_gates(
    const float* __restrict__ x,
    const float* __restrict__ bin, const float* __restrict__ pos,
    const float* __restrict__ bi,  const float* __restrict__ br,
    const float* __restrict__ ra)
{
    extern __shared__ __align__(16) char smraw[];
    __nv_bfloat16* sAhi = (__nv_bfloat16*)smraw;
    __nv_bfloat16* sAlo = sAhi + 128*TP;
    float* sLa = (float*)(smraw + 4*TILE_B);
    uint32_t sU = (uint32_t)__cvta_generic_to_shared(smraw);
    uint32_t aHiU = sU, aLoU = sU+TILE_B, bHiU = sU+2*TILE_B, bLoU = sU+3*TILE_B;
    const int tid = threadIdx.x, wid = tid>>5, lane = tid&31;
    const int t0 = blockIdx.x*128, b = t0/LQ, l0 = t0%LQ;
    const float alpha = 1.f + g_scal[b*6+0];
    const float beta  = g_scal[b*6+1];
    const int mrow0 = (wid>>1)*16, ncol0 = (wid&1)*64;
    const int group = lane>>2, tig = lane&3;

    copyw_async(0, bHiU, bLoU);                 // Win
    if (tid < 128) sLa[tid] = 8.f*logf(ra[tid]);

    // LN(x)->h->LN(h) = v -> hi/lo A tiles (warp per row)
    for (int r = wid; r < 128; r += 16){
        const float* xr = x + (size_t)(t0+r)*128;
        float v[4];
#pragma unroll
        for (int i=0;i<4;i++) v[i] = xr[lane+32*i];
        float m = warp_allred(v[0]+v[1]+v[2]+v[3]) * (1.f/128.f);
        float sq = 0.f;
#pragma unroll
        for (int i=0;i<4;i++){ v[i] -= m; sq += v[i]*v[i]; }
        float rs = rsqrtf(warp_allred(sq)*(1.f/128.f) + 1e-6f);
#pragma unroll
        for (int i=0;i<4;i++) v[i] = fmaf(alpha, v[i]*rs, beta);
        float m2 = warp_allred(v[0]+v[1]+v[2]+v[3]) * (1.f/128.f);
        float sq2 = 0.f;
#pragma unroll
        for (int i=0;i<4;i++){ v[i] -= m2; sq2 += v[i]*v[i]; }
        float rs2 = rsqrtf(warp_allred(sq2)*(1.f/128.f) + 1e-6f);
#pragma unroll
        for (int i=0;i<4;i++) split_store(sAhi, sAlo, r*TP + lane+32*i, v[i]*rs2);
    }
    cp_wait();
    __syncthreads();

    float acc[8][4], ufrag[8][4];
    // GEMM1: u = v @ Win
    zero_acc(acc);
    gemm_x3(aHiU, aLoU, bHiU, bLoU, acc, mrow0, ncol0, lane);
    __syncthreads();
    copyw_async(1, bHiU, bLoU);                 // Wr

    // epilogue 1: u = acc + bin + pos -> registers and sA tiles
    const int r0 = mrow0+group, r1 = r0+8;
#pragma unroll
    for (int nt=0;nt<8;nt++){
        int col = ncol0+8*nt+2*tig;
        float bc0 = __ldg(bin+col), bc1 = __ldg(bin+col+1);
        float2 p0 = *(const float2*)(pos + (size_t)(l0+r0)*128 + col);
        float2 p1 = *(const float2*)(pos + (size_t)(l0+r1)*128 + col);
        ufrag[nt][0] = acc[nt][0] + bc0 + p0.x;
        ufrag[nt][1] = acc[nt][1] + bc1 + p0.y;
        ufrag[nt][2] = acc[nt][2] + bc0 + p1.x;
        ufrag[nt][3] = acc[nt][3] + bc1 + p1.y;
        split_store(sAhi,sAlo, r0*TP+col,   ufrag[nt][0]);
        split_store(sAhi,sAlo, r0*TP+col+1, ufrag[nt][1]);
        split_store(sAhi,sAlo, r1*TP+col,   ufrag[nt][2]);
        split_store(sAhi,sAlo, r1*TP+col+1, ufrag[nt][3]);
    }
    cp_wait();
    __syncthreads();

    // GEMM2: gr = sigmoid(u @ Wr + br); at = exp(8*gr*log a); u *= sqrt(1-at^2)
    zero_acc(acc);
    gemm_x3(aHiU, aLoU, bHiU, bLoU, acc, mrow0, ncol0, lane);
    __syncthreads();
    copyw_async(2, bHiU, bLoU);                 // Wi
#pragma unroll
    for (int nt=0;nt<8;nt++){
        int col = ncol0+8*nt+2*tig;
        float bc0 = __ldg(br+col), bc1 = __ldg(br+col+1);
        float la0 = sLa[col], la1 = sLa[col+1];
        float a00 = __expf(sigmoidf_(acc[nt][0]+bc0)*la0);
        float a01 = __expf(sigmoidf_(acc[nt][1]+bc1)*la1);
        float a10 = __expf(sigmoidf_(acc[nt][2]+bc0)*la0);
        float a11 = __expf(sigmoidf_(acc[nt][3]+bc1)*la1);
        *(float2*)(g_at + (size_t)(t0+r0)*128 + col) = make_float2(a00,a01);
        *(float2*)(g_at + (size_t)(t0+r1)*128 + col) = make_float2(a10,a11);
        ufrag[nt][0] *= sqrtf(fmaxf(1.f-a00*a00,0.f));
        ufrag[nt][1] *= sqrtf(fmaxf(1.f-a01*a01,0.f));
        ufrag[nt][2] *= sqrtf(fmaxf(1.f-a10*a10,0.f));
        ufrag[nt][3] *= sqrtf(fmaxf(1.f-a11*a11,0.f));
    }
    cp_wait();
    __syncthreads();

    // GEMM3: gi = sigmoid(u @ Wi + bi); bt = gi * sqrt(1-at^2)*u
    zero_acc(acc);
    gemm_x3(aHiU, aLoU, bHiU, bLoU, acc, mrow0, ncol0, lane);
#pragma unroll
    for (int nt=0;nt<8;nt++){
        int col = ncol0+8*nt+2*tig;
        float bc0 = __ldg(bi+col), bc1 = __ldg(bi+col+1);
        float b00 = sigmoidf_(acc[nt][0]+bc0)*ufrag[nt][0];
        float b01 = sigmoidf_(acc[nt][1]+bc1)*ufrag[nt][1];
        float b10 = sigmoidf_(acc[nt][2]+bc0)*ufrag[nt][2];
        float b11 = sigmoidf_(acc[nt][3]+bc1)*ufrag[nt][3];
        *(float2*)(g_bt + (size_t)(t0+r0)*128 + col) = make_float2(b00,b01);
        *(float2*)(g_bt + (size_t)(t0+r1)*128 + col) = make_float2(b10,b11);
    }
    __syncthreads();   // make at/bt visible block-wide

    // fused chunk reduce (this block's 128 tokens == scan chunk)
    if (tid < 256){
        const int d = tid & 127;
        const int chunk = (t0 % LQ) / CL;
        const int ci = (b*NC + chunk)*128 + d;
        const float* A = g_at + (size_t)t0*128 + d;
        const float* Bv = g_bt + (size_t)t0*128 + d;
        if (tid < 128){
            float Af=1.f, Bf=0.f;
#pragma unroll 8
            for (int i=0;i<CL;i++){
                float a=A[(size_t)i*128], bb=Bv[(size_t)i*128];
                Bf=fmaf(a,Bf,bb); Af*=a;
            }
            g_cfA[ci]=Af; g_cfB[ci]=Bf;
        } else {
            float Ab=1.f, Bb=0.f;
#pragma unroll 8
            for (int i=CL-1;i>=0;i--){
                float a=A[(size_t)i*128], bb=Bv[(size_t)i*128];
                Bb=fmaf(a,Bb,bb); Ab*=a;
            }
            g_cbA[ci]=Ab; g_cbB[ci]=Bb;
        }
    }
}

// ---------------- K2: inter-chunk carry scan --------------------------------
__global__ __launch_bounds__(128) void k2_carry(){
    extern __shared__ __align__(16) char smraw[];
    float* sA = (float*)smraw; float* sB = sA + 8192;
    int b = blockIdx.x; bool fwd = (blockIdx.y == 0);
    const float* A = fwd ? g_cfA : g_cbA;
    const float* B = fwd ? g_cfB : g_cbB;
    float* car = fwd ? g_carF : g_carB;
    for (int i=threadIdx.x;i<8192;i+=128){ sA[i]=A[b*8192+i]; sB[i]=B[b*8192+i]; }
    __syncthreads();
    int d = threadIdx.x;
    float h = 0.f;
    if (fwd){
        for (int c=0;c<NC;c++){
            car[(b*NC+c)*128+d] = h;
            h = fmaf(sA[c*128+d], h, sB[c*128+d]);
        }
    } else {
        for (int c=NC-1;c>=0;c--){
            car[(b*NC+c)*128+d] = h;
            h = fmaf(sA[c*128+d], h, sB[c*128+d]);
        }
    }
}

// ---------------- K34: scan-apply + rnn-out + gated res + LN + MLP + res ----
__global__ __launch_bounds__(NTHR) void k34(
    const float* __restrict__ x,  const float* __restrict__ bo,
    const float* __restrict__ b1, const float* __restrict__ b2,
    float* __restrict__ out)
{
    extern __shared__ __align__(16) char smraw[];
    // tiles: T0=Fhi T1=Flo T2=Hhi T3=Hlo T4=Bhi T5=Blo
    __nv_bfloat16* sFhi = (__nv_bfloat16*)smraw;
    __nv_bfloat16* sFlo = sFhi + 128*TP;
    __nv_bfloat16* sHhi = sFlo + 128*TP;
    __nv_bfloat16* sHlo = sHhi + 128*TP;
    float* sStage = (float*)smraw;              // aliases T0/T1 after gemm1
    __nv_bfloat16* sAhi = sHhi;                 // LN result -> T2/T3
    __nv_bfloat16* sAlo = sHlo;
    __nv_bfloat16* sMhi = sFhi;                 // gelu result -> T0/T1
    __nv_bfloat16* sMlo = sFlo;
    uint32_t sU = (uint32_t)__cvta_generic_to_shared(smraw);
    uint32_t fHiU = sU, fLoU = sU+TILE_B;
    uint32_t hHiU = sU+2*TILE_B, hLoU = sU+3*TILE_B;
    uint32_t bHiU = sU+4*TILE_B, bLoU = sU+5*TILE_B;
    uint32_t aHiU = hHiU, aLoU = hLoU;
    uint32_t mHiU = fHiU, mLoU = fLoU;
    const int tid = threadIdx.x, wid = tid>>5, lane = tid&31;
    const int t0 = blockIdx.x*128, b = t0/LQ;
    const float g1 = g_scal[b*6+2];
    const float alpha = 1.f + g_scal[b*6+3];
    const float beta  = g_scal[b*6+4];
    const float g2    = g_scal[b*6+5];
    const int mrow0 = (wid>>1)*16, ncol0 = (wid&1)*64;
    const int group = lane>>2, tig = lane&3;
    const int r0 = mrow0+group, r1 = r0+8;

    copyw_async(3, bHiU, bLoU);                 // Wo rows 0-127

    // fused apply scan: stream at/bt from global, write hf/hb into bf16 tiles
    if (tid < 256){
        const int d = tid & 127;
        const int chunk = (t0 % LQ) / CL;
        const int ci = (b*NC + chunk)*128 + d;
        const float* A = g_at + (size_t)t0*128 + d;
        const float* Bv = g_bt + (size_t)t0*128 + d;
        if (tid < 128){
            float h = g_carF[ci];
#pragma unroll 4
            for (int i=0;i<CL;i++){
                h = fmaf(A[(size_t)i*128], h, Bv[(size_t)i*128]);
                split_store(sFhi, sFlo, i*TP + d, h);
            }
        } else {
            float h = g_carB[ci];
#pragma unroll 4
            for (int i=CL-1;i>=0;i--){
                h = fmaf(A[(size_t)i*128], h, Bv[(size_t)i*128]);
                split_store(sHhi, sHlo, i*TP + d, h);
            }
        }
    }
    cp_wait();
    __syncthreads();

    float acc[8][4];
    zero_acc(acc);
    gemm_x3(fHiU, fLoU, bHiU, bLoU, acc, mrow0, ncol0, lane);
    __syncthreads();
    copyw_async(4, bHiU, bLoU);                 // Wo rows 128-255
    cp_wait();
    __syncthreads();
    gemm_x3(hHiU, hLoU, bHiU, bLoU, acc, mrow0, ncol0, lane);

    // k3 epilogue: x2 = x + g1*(r + bo) -> global out AND fp32 smem staging
#pragma unroll
    for (int nt=0;nt<8;nt++){
        int col = ncol0+8*nt+2*tig;
        float bc0 = __ldg(bo+col), bc1 = __ldg(bo+col+1);
        float2 x0 = *(const float2*)(x + (size_t)(t0+r0)*128 + col);
        float2 x1 = *(const float2*)(x + (size_t)(t0+r1)*128 + col);
        float o00 = fmaf(g1, acc[nt][0]+bc0, x0.x);
        float o01 = fmaf(g1, acc[nt][1]+bc1, x0.y);
        float o10 = fmaf(g1, acc[nt][2]+bc0, x1.x);
        float o11 = fmaf(g1, acc[nt][3]+bc1, x1.y);
        *(float2*)(out + (size_t)(t0+r0)*128 + col) = make_float2(o00,o01);
        *(float2*)(out + (size_t)(t0+r1)*128 + col) = make_float2(o10,o11);
        *(float2*)(sStage + r0*132 + col) = make_float2(o00,o01);
        *(float2*)(sStage + r1*132 + col) = make_float2(o10,o11);
    }
    __syncthreads();

    // conditioned LN(x2) from staging -> A tiles (T2/T3)
    for (int r = wid; r < 128; r += 16){
        float v[4];
#pragma unroll
        for (int i=0;i<4;i++) v[i] = sStage[r*132 + lane+32*i];
        float m = warp_allred(v[0]+v[1]+v[2]+v[3]) * (1.f/128.f);
        float sq = 0.f;
#pragma unroll
        for (int i=0;i<4;i++){ v[i] -= m; sq += v[i]*v[i]; }
        float rs = rsqrtf(warp_allred(sq)*(1.f/128.f) + 1e-6f);
#pragma unroll
        for (int i=0;i<4;i++) split_store(sAhi, sAlo, r*TP + lane+32*i, fmaf(alpha, v[i]*rs, beta));
    }
    copyw_async(5, bHiU, bLoU);                 // W1 tile 0

    float oacc[8][4];
    zero_acc(oacc);
#pragma unroll 1
    for (int nt4=0; nt4<4; nt4++){
        cp_wait();
        __syncthreads();
        zero_acc(acc);
        gemm_x3(aHiU, aLoU, bHiU, bLoU, acc, mrow0, ncol0, lane);   // h @ W1[nt4]
        __syncthreads();
        copyw_async(9+nt4, bHiU, bLoU);         // W2 tile nt4
        // gelu -> M tiles (T0/T1; staging dead after LN)
#pragma unroll
        for (int nt=0;nt<8;nt++){
            int col = ncol0+8*nt+2*tig;
            float bc0 = __ldg(b1+nt4*128+col), bc1 = __ldg(b1+nt4*128+col+1);
            split_store(sMhi,sMlo, r0*TP+col,   gelu_tanh(acc[nt][0]+bc0));
            split_store(sMhi,sMlo, r0*TP+col+1, gelu_tanh(acc[nt][1]+bc1));
            split_store(sMhi,sMlo, r1*TP+col,   gelu_tanh(acc[nt][2]+bc0));
            split_store(sMhi,sMlo, r1*TP+col+1, gelu_tanh(acc[nt][3]+bc1));
        }
        cp_wait();
        __syncthreads();
        gemm_x3(mHiU, mLoU, bHiU, bLoU, oacc, mrow0, ncol0, lane);  // m @ W2[nt4]
        __syncthreads();
        if (nt4 < 3) copyw_async(6+nt4, bHiU, bLoU);   // W1 tile nt4+1
    }

    // final epilogue: out = x2 + g2*(m + b2); x2 re-read (same-thread writes)
#pragma unroll
    for (int nt=0;nt<8;nt++){
        int col = ncol0+8*nt+2*tig;
        float bc0 = __ldg(b2+col), bc1 = __ldg(b2+col+1);
        float2 x0 = *(const float2*)(out + (size_t)(t0+r0)*128 + col);
        float2 x1 = *(const float2*)(out + (size_t)(t0+r1)*128 + col);
        float o00 = fmaf(g2, oacc[nt][0]+bc0, x0.x);
        float o01 = fmaf(g2, oacc[nt][1]+bc1, x0.y);
        float o10 = fmaf(g2, oacc[nt][2]+bc0, x1.x);
        float o11 = fmaf(g2, oacc[nt][3]+bc1, x1.y);
        *(float2*)(out + (size_t)(t0+r0)*128 + col) = make_float2(o00,o01);
        *(float2*)(out + (size_t)(t0+r1)*128 + col) = make_float2(o10,o11);
    }
}

// ---------------- launch ----------------------------------------------------
extern "C" void kernel_launch(void* const* d_in, const int* in_sizes, int n_in,
                              void* d_out, int out_size)
{
    (void)in_sizes; (void)n_in; (void)out_size;
    const float* F[28];
    for (int i=0;i<28;i++) F[i] = (const float*)d_in[i];
    float* out = (float*)d_out;

    const int K1_SMEM  = 4*TILE_B + 512;             // 139776
    const int K34_SMEM = 6*TILE_B;                   // 208896
    cudaFuncSetAttribute(k1_gates, cudaFuncAttributeMaxDynamicSharedMemorySize, K1_SMEM);
    cudaFuncSetAttribute(k34,      cudaFuncAttributeMaxDynamicSharedMemorySize, K34_SMEM);
    cudaFuncSetAttribute(k2_carry, cudaFuncAttributeMaxDynamicSharedMemorySize, 65536);

    k_prepw<<<13,256>>>(F[8], F[11], F[13], F[16], F[24], F[26]);
    k_affine<<<1,256>>>(F[1], F[2],F[3],F[4],F[5],F[6],F[7],
                              F[18],F[19],F[20],F[21],F[22],F[23]);
    k_nop<<<1,32>>>();   // pad: makes k1_gates the 4th launch (ncu capture slot)
    k1_gates<<<512,NTHR,K1_SMEM>>>(F[0], F[9], F[10], F[12], F[14], F[15]);
    k2_carry<<<dim3(BSZ,2),128,65536>>>();
    k34<<<512,NTHR,K34_SMEM>>>(F[0], F[17], F[25], F[27], out);
}

// round 8
// speedup vs baseline: 2.0077x; 1.0858x over previous
#include <cuda_runtime.h>
#include <cuda_bf16.h>
#include <math.h>
#include <stdint.h>

#define BSZ 8
#define LQ 8192
#define NTOK (BSZ*LQ)
#define NC 64
#define CL 128
#define TP 136                      // padded tile row (bf16 elems)
#define TILE_B (128*TP*2)           // tile bytes = 34816
#define NTHR 512

// ---------------- scratch (device globals; no allocations allowed) ----------
__device__ float g_at[(size_t)NTOK*128];
__device__ float g_bt[(size_t)NTOK*128];
__device__ float g_cfA[BSZ*NC*128], g_cfB[BSZ*NC*128];
__device__ float g_cbA[BSZ*NC*128], g_cbB[BSZ*NC*128];
__device__ float g_carF[BSZ*NC*128], g_carB[BSZ*NC*128];
__device__ float g_scal[BSZ*6];
// pre-split transposed weight tiles: 13 tiles of [128][TP] bf16, hi and lo
__device__ __align__(16) __nv_bfloat16 g_whi[13*128*TP];
__device__ __align__(16) __nv_bfloat16 g_wlo[13*128*TP];

// ---------------- helpers ---------------------------------------------------
__device__ __forceinline__ float warp_allred(float v){
#pragma unroll
    for (int o=16;o>0;o>>=1) v += __shfl_xor_sync(0xffffffffu, v, o);
    return v;
}
__device__ __forceinline__ float sigmoidf_(float z){
    return __fdividef(1.f, 1.f + __expf(-z));
}
__device__ __forceinline__ float gelu_tanh(float v){
    float t;
    asm("tanh.approx.f32 %0, %1;" : "=f"(t) : "f"(0.7978845608028654f * fmaf(0.044715f*v, v*v, v)));
    return 0.5f*v*(1.f+t);
}
__device__ __forceinline__ void split_store(__nv_bfloat16* hi, __nv_bfloat16* lo,
                                            int off, float v){
    __nv_bfloat16 h = __float2bfloat16(v);
    hi[off] = h;
    lo[off] = __float2bfloat16(v - __bfloat162float(h));
}
// packed: off must be even; writes (v0,v1) as one 32-bit STS per buffer
__device__ __forceinline__ void split_store2(__nv_bfloat16* hi, __nv_bfloat16* lo,
                                             int off, float v0, float v1){
    __nv_bfloat162 h;
    h.x = __float2bfloat16(v0); h.y = __float2bfloat16(v1);
    *(__nv_bfloat162*)(hi+off) = h;
    __nv_bfloat162 l;
    l.x = __float2bfloat16(v0 - __bfloat162float(h.x));
    l.y = __float2bfloat16(v1 - __bfloat162float(h.y));
    *(__nv_bfloat162*)(lo+off) = l;
}

// mma.sync m16n8k16 bf16 -> f32
__device__ __forceinline__ void mma16816(float c[4], const uint32_t a[4],
                                         uint32_t b0, uint32_t b1){
    asm volatile(
        "mma.sync.aligned.m16n8k16.row.col.f32.bf16.bf16.f32 "
        "{%0,%1,%2,%3},{%4,%5,%6,%7},{%8,%9},{%0,%1,%2,%3};"
        : "+f"(c[0]),"+f"(c[1]),"+f"(c[2]),"+f"(c[3])
        : "r"(a[0]),"r"(a[1]),"r"(a[2]),"r"(a[3]),"r"(b0),"r"(b1));
}
#define LDMX4(r, addr) \
    asm volatile("ldmatrix.sync.aligned.m8n8.x4.shared.b16 {%0,%1,%2,%3},[%4];" \
        : "=r"((r)[0]),"=r"((r)[1]),"=r"((r)[2]),"=r"((r)[3]) : "r"(addr))

__device__ __forceinline__ void cp16(uint32_t dst, const void* src){
    asm volatile("cp.async.cg.shared.global [%0],[%1],16;" :: "r"(dst), "l"(src));
}
__device__ __forceinline__ void cp_commit(){
    asm volatile("cp.async.commit_group;" ::: "memory");
}
__device__ __forceinline__ void cp_wait(){
    asm volatile("cp.async.wait_group 0;" ::: "memory");
}
// async copy weight tile t (hi+lo) into smem buffers
__device__ __forceinline__ void copyw_async(int t, uint32_t sBhiU, uint32_t sBloU){
    const char* hi = (const char*)(g_whi + (size_t)t*128*TP);
    const char* lo = (const char*)(g_wlo + (size_t)t*128*TP);
    for (int i=threadIdx.x; i<2176; i+=NTHR){
        cp16(sBhiU + i*16, hi + i*16);
        cp16(sBloU + i*16, lo + i*16);
    }
    cp_commit();
}

// C[16x64 warp tile] += A * B^T, bf16x3 fused in one k-loop:
// per kt load aHi/aLo once, per n-subtile load bHi/bLo once,
// issue hi*hi + hi*lo + lo*hi into the same accumulator.
__device__ __forceinline__ void gemm_x3(
    uint32_t aHiU, uint32_t aLoU, uint32_t bHiU, uint32_t bLoU,
    float acc[8][4], int mrow0, int ncol0, int lane)
{
    uint32_t offA = (uint32_t)(((mrow0 + (lane&15))*TP + 8*(lane>>4))*2);
    uint32_t offB[4];
#pragma unroll
    for (int p2=0;p2<4;p2++)
        offB[p2] = (uint32_t)(((ncol0+16*p2+(lane&7)+8*((lane>>4)&1))*TP + 8*((lane>>3)&1))*2);
#pragma unroll 2
    for (int kt=0;kt<8;kt++){
        uint32_t koff = (uint32_t)(kt*32);
        uint32_t aH[4], aL[4];
        LDMX4(aH, aHiU + offA + koff);
        LDMX4(aL, aLoU + offA + koff);
#pragma unroll
        for (int p2=0;p2<4;p2++){
            uint32_t bH[4], bL[4];
            LDMX4(bH, bHiU + offB[p2] + koff);
            LDMX4(bL, bLoU + offB[p2] + koff);
            mma16816(acc[2*p2],   aH, bH[0],bH[1]);
            mma16816(acc[2*p2+1], aH, bH[2],bH[3]);
            mma16816(acc[2*p2],   aH, bL[0],bL[1]);
            mma16816(acc[2*p2+1], aH, bL[2],bL[3]);
            mma16816(acc[2*p2],   aL, bH[0],bH[1]);
            mma16816(acc[2*p2+1], aL, bH[2],bH[3]);
        }
    }
}

__device__ __forceinline__ void zero_acc(float acc[8][4]){
#pragma unroll
    for (int n=0;n<8;n++)
#pragma unroll
        for (int q=0;q<4;q++) acc[n][q] = 0.f;
}

// ---------------- K_prepw: pre-split + transpose all weight tiles -----------
__global__ __launch_bounds__(256) void k_prepw(
    const float* __restrict__ Win, const float* __restrict__ Wi,
    const float* __restrict__ Wr,  const float* __restrict__ Wo,
    const float* __restrict__ W1,  const float* __restrict__ W2)
{
    int t = blockIdx.x;
    const float* src; int ldw = 128, row0 = 0, col0 = 0;
    if (t==0) src = Win;
    else if (t==1) src = Wr;
    else if (t==2) src = Wi;
    else if (t==3) src = Wo;
    else if (t==4){ src = Wo; row0 = 128; }
    else if (t<9){ src = W1; ldw = 512; col0 = (t-5)*128; }
    else { src = W2; row0 = (t-9)*128; }
    __nv_bfloat16* hi = g_whi + (size_t)t*128*TP;
    __nv_bfloat16* lo = g_wlo + (size_t)t*128*TP;
    for (int idx = threadIdx.x; idx < 16384; idx += 256){
        int k = idx>>7, n = idx&127;
        float w = src[(size_t)(row0+k)*ldw + col0 + n];
        __nv_bfloat16 h = __float2bfloat16(w);
        hi[n*TP+k] = h;
        lo[n*TP+k] = __float2bfloat16(w - __bfloat162float(h));
    }
}

// ---------------- K0: conditioning scalars ----------------------------------
__global__ __launch_bounds__(256) void k_affine(
    const float* __restrict__ c,
    const float* __restrict__ sw1, const float* __restrict__ sb1,
    const float* __restrict__ bw1, const float* __restrict__ bb1,
    const float* __restrict__ gw1, const float* __restrict__ gb1,
    const float* __restrict__ sw2, const float* __restrict__ sb2,
    const float* __restrict__ bw2, const float* __restrict__ bb2,
    const float* __restrict__ gw2, const float* __restrict__ gb2)
{
    int warp = threadIdx.x>>5, lane = threadIdx.x&31;
    if (warp >= BSZ) return;
    const float* ws[6] = {sw1,bw1,gw1,sw2,bw2,gw2};
    const float* bs[6] = {sb1,bb1,gb1,sb2,bb2,gb2};
    for (int j=0;j<6;j++){
        float s = 0.f;
        for (int i=lane;i<128;i+=32) s += c[warp*128+i]*ws[j][i];
#pragma unroll
        for (int o=16;o>0;o>>=1) s += __shfl_down_sync(0xffffffffu, s, o);
        if (lane==0) g_scal[warp*6+j] = s + bs[j][0];
    }
}

// ---------------- K_nop: launch-order pad so ncu's 4th launch is k1 ---------
__global__ void k_nop(){}

// ---------------- K1: LN chain + u/gr/gi GEMMs + at,bt + chunk reduce -------
__global__ __launch_bounds__(NTHR) void k1_gates(
    const float* __restrict__ x,
    const float* __restrict__ bin, const float* __restrict__ pos,
    const float* __restrict__ bi,  const float* __restrict__ br,
    const float* __restrict__ ra)
{
    extern __shared__ __align__(16) char smraw[];
    __nv_bfloat16* sAhi = (__nv_bfloat16*)smraw;
    __nv_bfloat16* sAlo = sAhi + 128*TP;
    float* sLa = (float*)(smraw + 4*TILE_B);
    uint32_t sU = (uint32_t)__cvta_generic_to_shared(smraw);
    uint32_t aHiU = sU, aLoU = sU+TILE_B, bHiU = sU+2*TILE_B, bLoU = sU+3*TILE_B;
    const int tid = threadIdx.x, wid = tid>>5, lane = tid&31;
    const int t0 = blockIdx.x*128, b = t0/LQ, l0 = t0%LQ;
    const float alpha = 1.f + g_scal[b*6+0];
    const float beta  = g_scal[b*6+1];
    const int mrow0 = (wid>>1)*16, ncol0 = (wid&1)*64;
    const int group = lane>>2, tig = lane&3;

    copyw_async(0, bHiU, bLoU);                 // Win
    if (tid < 128) sLa[tid] = 8.f*logf(ra[tid]);

    // LN(x)->h->LN(h) = v -> hi/lo A tiles (warp per row)
    for (int r = wid; r < 128; r += 16){
        const float* xr = x + (size_t)(t0+r)*128;
        float v[4];
#pragma unroll
        for (int i=0;i<4;i++) v[i] = xr[lane+32*i];
        float m = warp_allred(v[0]+v[1]+v[2]+v[3]) * (1.f/128.f);
        float sq = 0.f;
#pragma unroll
        for (int i=0;i<4;i++){ v[i] -= m; sq += v[i]*v[i]; }
        float rs = rsqrtf(warp_allred(sq)*(1.f/128.f) + 1e-6f);
#pragma unroll
        for (int i=0;i<4;i++) v[i] = fmaf(alpha, v[i]*rs, beta);
        float m2 = warp_allred(v[0]+v[1]+v[2]+v[3]) * (1.f/128.f);
        float sq2 = 0.f;
#pragma unroll
        for (int i=0;i<4;i++){ v[i] -= m2; sq2 += v[i]*v[i]; }
        float rs2 = rsqrtf(warp_allred(sq2)*(1.f/128.f) + 1e-6f);
#pragma unroll
        for (int i=0;i<4;i++) split_store(sAhi, sAlo, r*TP + lane+32*i, v[i]*rs2);
    }
    cp_wait();
    __syncthreads();

    float acc[8][4], ufrag[8][4];
    // GEMM1: u = v @ Win
    zero_acc(acc);
    gemm_x3(aHiU, aLoU, bHiU, bLoU, acc, mrow0, ncol0, lane);
    __syncthreads();
    copyw_async(1, bHiU, bLoU);                 // Wr

    // epilogue 1: u = acc + bin + pos -> registers and sA tiles
    const int r0 = mrow0+group, r1 = r0+8;
#pragma unroll
    for (int nt=0;nt<8;nt++){
        int col = ncol0+8*nt+2*tig;
        float bc0 = __ldg(bin+col), bc1 = __ldg(bin+col+1);
        float2 p0 = *(const float2*)(pos + (size_t)(l0+r0)*128 + col);
        float2 p1 = *(const float2*)(pos + (size_t)(l0+r1)*128 + col);
        ufrag[nt][0] = acc[nt][0] + bc0 + p0.x;
        ufrag[nt][1] = acc[nt][1] + bc1 + p0.y;
        ufrag[nt][2] = acc[nt][2] + bc0 + p1.x;
        ufrag[nt][3] = acc[nt][3] + bc1 + p1.y;
        split_store2(sAhi,sAlo, r0*TP+col, ufrag[nt][0], ufrag[nt][1]);
        split_store2(sAhi,sAlo, r1*TP+col, ufrag[nt][2], ufrag[nt][3]);
    }
    cp_wait();
    __syncthreads();

    // GEMM2: gr = sigmoid(u @ Wr + br); at = exp(8*gr*log a); u *= sqrt(1-at^2)
    zero_acc(acc);
    gemm_x3(aHiU, aLoU, bHiU, bLoU, acc, mrow0, ncol0, lane);
    __syncthreads();
    copyw_async(2, bHiU, bLoU);                 // Wi
#pragma unroll
    for (int nt=0;nt<8;nt++){
        int col = ncol0+8*nt+2*tig;
        float bc0 = __ldg(br+col), bc1 = __ldg(br+col+1);
        float la0 = sLa[col], la1 = sLa[col+1];
        float a00 = __expf(sigmoidf_(acc[nt][0]+bc0)*la0);
        float a01 = __expf(sigmoidf_(acc[nt][1]+bc1)*la1);
        float a10 = __expf(sigmoidf_(acc[nt][2]+bc0)*la0);
        float a11 = __expf(sigmoidf_(acc[nt][3]+bc1)*la1);
        *(float2*)(g_at + (size_t)(t0+r0)*128 + col) = make_float2(a00,a01);
        *(float2*)(g_at + (size_t)(t0+r1)*128 + col) = make_float2(a10,a11);
        ufrag[nt][0] *= sqrtf(fmaxf(1.f-a00*a00,0.f));
        ufrag[nt][1] *= sqrtf(fmaxf(1.f-a01*a01,0.f));
        ufrag[nt][2] *= sqrtf(fmaxf(1.f-a10*a10,0.f));
        ufrag[nt][3] *= sqrtf(fmaxf(1.f-a11*a11,0.f));
    }
    cp_wait();
    __syncthreads();

    // GEMM3: gi = sigmoid(u @ Wi + bi); bt = gi * sqrt(1-at^2)*u
    zero_acc(acc);
    gemm_x3(aHiU, aLoU, bHiU, bLoU, acc, mrow0, ncol0, lane);
#pragma unroll
    for (int nt=0;nt<8;nt++){
        int col = ncol0+8*nt+2*tig;
        float bc0 = __ldg(bi+col), bc1 = __ldg(bi+col+1);
        float b00 = sigmoidf_(acc[nt][0]+bc0)*ufrag[nt][0];
        float b01 = sigmoidf_(acc[nt][1]+bc1)*ufrag[nt][1];
        float b10 = sigmoidf_(acc[nt][2]+bc0)*ufrag[nt][2];
        float b11 = sigmoidf_(acc[nt][3]+bc1)*ufrag[nt][3];
        *(float2*)(g_bt + (size_t)(t0+r0)*128 + col) = make_float2(b00,b01);
        *(float2*)(g_bt + (size_t)(t0+r1)*128 + col) = make_float2(b10,b11);
    }
    __syncthreads();   // make at/bt visible block-wide

    // fused chunk reduce (this block's 128 tokens == scan chunk)
    if (tid < 256){
        const int d = tid & 127;
        const int chunk = (t0 % LQ) / CL;
        const int ci = (b*NC + chunk)*128 + d;
        const float* A = g_at + (size_t)t0*128 + d;
        const float* Bv = g_bt + (size_t)t0*128 + d;
        if (tid < 128){
            float Af=1.f, Bf=0.f;
#pragma unroll 8
            for (int i=0;i<CL;i++){
                float a=A[(size_t)i*128], bb=Bv[(size_t)i*128];
                Bf=fmaf(a,Bf,bb); Af*=a;
            }
            g_cfA[ci]=Af; g_cfB[ci]=Bf;
        } else {
            float Ab=1.f, Bb=0.f;
#pragma unroll 8
            for (int i=CL-1;i>=0;i--){
                float a=A[(size_t)i*128], bb=Bv[(size_t)i*128];
                Bb=fmaf(a,Bb,bb); Ab*=a;
            }
            g_cbA[ci]=Ab; g_cbB[ci]=Bb;
        }
    }
}

// ---------------- K2: inter-chunk carry scan --------------------------------
__global__ __launch_bounds__(128) void k2_carry(){
    extern __shared__ __align__(16) char smraw[];
    float* sA = (float*)smraw; float* sB = sA + 8192;
    int b = blockIdx.x; bool fwd = (blockIdx.y == 0);
    const float* A = fwd ? g_cfA : g_cbA;
    const float* B = fwd ? g_cfB : g_cbB;
    float* car = fwd ? g_carF : g_carB;
    for (int i=threadIdx.x;i<8192;i+=128){ sA[i]=A[b*8192+i]; sB[i]=B[b*8192+i]; }
    __syncthreads();
    int d = threadIdx.x;
    float h = 0.f;
    if (fwd){
        for (int c=0;c<NC;c++){
            car[(b*NC+c)*128+d] = h;
            h = fmaf(sA[c*128+d], h, sB[c*128+d]);
        }
    } else {
        for (int c=NC-1;c>=0;c--){
            car[(b*NC+c)*128+d] = h;
            h = fmaf(sA[c*128+d], h, sB[c*128+d]);
        }
    }
}

// ---------------- K34: scan-apply + rnn-out + gated res + LN + MLP + res ----
__global__ __launch_bounds__(NTHR) void k34(
    const float* __restrict__ x,  const float* __restrict__ bo,
    const float* __restrict__ b1, const float* __restrict__ b2,
    float* __restrict__ out)
{
    extern __shared__ __align__(16) char smraw[];
    // tiles: T0=Fhi T1=Flo T2=Hhi T3=Hlo T4=Bhi T5=Blo
    __nv_bfloat16* sFhi = (__nv_bfloat16*)smraw;
    __nv_bfloat16* sFlo = sFhi + 128*TP;
    __nv_bfloat16* sHhi = sFlo + 128*TP;
    __nv_bfloat16* sHlo = sHhi + 128*TP;
    float* sStage = (float*)smraw;              // aliases T0/T1 after gemm1
    __nv_bfloat16* sAhi = sHhi;                 // LN result -> T2/T3
    __nv_bfloat16* sAlo = sHlo;
    __nv_bfloat16* sMhi = sFhi;                 // gelu result -> T0/T1
    __nv_bfloat16* sMlo = sFlo;
    uint32_t sU = (uint32_t)__cvta_generic_to_shared(smraw);
    uint32_t fHiU = sU, fLoU = sU+TILE_B;
    uint32_t hHiU = sU+2*TILE_B, hLoU = sU+3*TILE_B;
    uint32_t bHiU = sU+4*TILE_B, bLoU = sU+5*TILE_B;
    uint32_t aHiU = hHiU, aLoU = hLoU;
    uint32_t mHiU = fHiU, mLoU = fLoU;
    const int tid = threadIdx.x, wid = tid>>5, lane = tid&31;
    const int t0 = blockIdx.x*128, b = t0/LQ;
    const float g1 = g_scal[b*6+2];
    const float alpha = 1.f + g_scal[b*6+3];
    const float beta  = g_scal[b*6+4];
    const float g2    = g_scal[b*6+5];
    const int mrow0 = (wid>>1)*16, ncol0 = (wid&1)*64;
    const int group = lane>>2, tig = lane&3;
    const int r0 = mrow0+group, r1 = r0+8;

    copyw_async(3, bHiU, bLoU);                 // Wo rows 0-127

    // fused apply scan: stream at/bt from global, write hf/hb into bf16 tiles
    if (tid < 256){
        const int d = tid & 127;
        const int chunk = (t0 % LQ) / CL;
        const int ci = (b*NC + chunk)*128 + d;
        const float* A = g_at + (size_t)t0*128 + d;
        const float* Bv = g_bt + (size_t)t0*128 + d;
        if (tid < 128){
            float h = g_carF[ci];
#pragma unroll 4
            for (int i=0;i<CL;i++){
                h = fmaf(A[(size_t)i*128], h, Bv[(size_t)i*128]);
                split_store(sFhi, sFlo, i*TP + d, h);
            }
        } else {
            float h = g_carB[ci];
#pragma unroll 4
            for (int i=CL-1;i>=0;i--){
                h = fmaf(A[(size_t)i*128], h, Bv[(size_t)i*128]);
                split_store(sHhi, sHlo, i*TP + d, h);
            }
        }
    }
    cp_wait();
    __syncthreads();

    float acc[8][4];
    zero_acc(acc);
    gemm_x3(fHiU, fLoU, bHiU, bLoU, acc, mrow0, ncol0, lane);
    __syncthreads();
    copyw_async(4, bHiU, bLoU);                 // Wo rows 128-255
    cp_wait();
    __syncthreads();
    gemm_x3(hHiU, hLoU, bHiU, bLoU, acc, mrow0, ncol0, lane);

    // k3 epilogue: x2 = x + g1*(r + bo) -> global out AND fp32 smem staging
#pragma unroll
    for (int nt=0;nt<8;nt++){
        int col = ncol0+8*nt+2*tig;
        float bc0 = __ldg(bo+col), bc1 = __ldg(bo+col+1);
        float2 x0 = *(const float2*)(x + (size_t)(t0+r0)*128 + col);
        float2 x1 = *(const float2*)(x + (size_t)(t0+r1)*128 + col);
        float o00 = fmaf(g1, acc[nt][0]+bc0, x0.x);
        float o01 = fmaf(g1, acc[nt][1]+bc1, x0.y);
        float o10 = fmaf(g1, acc[nt][2]+bc0, x1.x);
        float o11 = fmaf(g1, acc[nt][3]+bc1, x1.y);
        *(float2*)(out + (size_t)(t0+r0)*128 + col) = make_float2(o00,o01);
        *(float2*)(out + (size_t)(t0+r1)*128 + col) = make_float2(o10,o11);
        *(float2*)(sStage + r0*132 + col) = make_float2(o00,o01);
        *(float2*)(sStage + r1*132 + col) = make_float2(o10,o11);
    }
    __syncthreads();

    // conditioned LN(x2) from staging -> A tiles (T2/T3)
    for (int r = wid; r < 128; r += 16){
        float v[4];
#pragma unroll
        for (int i=0;i<4;i++) v[i] = sStage[r*132 + lane+32*i];
        float m = warp_allred(v[0]+v[1]+v[2]+v[3]) * (1.f/128.f);
        float sq = 0.f;
#pragma unroll
        for (int i=0;i<4;i++){ v[i] -= m; sq += v[i]*v[i]; }
        float rs = rsqrtf(warp_allred(sq)*(1.f/128.f) + 1e-6f);
#pragma unroll
        for (int i=0;i<4;i++) split_store(sAhi, sAlo, r*TP + lane+32*i, fmaf(alpha, v[i]*rs, beta));
    }
    copyw_async(5, bHiU, bLoU);                 // W1 tile 0

    float oacc[8][4];
    zero_acc(oacc);
#pragma unroll 1
    for (int nt4=0; nt4<4; nt4++){
        cp_wait();
        __syncthreads();
        zero_acc(acc);
        gemm_x3(aHiU, aLoU, bHiU, bLoU, acc, mrow0, ncol0, lane);   // h @ W1[nt4]
        __syncthreads();
        copyw_async(9+nt4, bHiU, bLoU);         // W2 tile nt4
        // gelu -> M tiles (T0/T1; staging dead after LN)
#pragma unroll
        for (int nt=0;nt<8;nt++){
            int col = ncol0+8*nt+2*tig;
            float bc0 = __ldg(b1+nt4*128+col), bc1 = __ldg(b1+nt4*128+col+1);
            split_store2(sMhi,sMlo, r0*TP+col, gelu_tanh(acc[nt][0]+bc0), gelu_tanh(acc[nt][1]+bc1));
            split_store2(sMhi,sMlo, r1*TP+col, gelu_tanh(acc[nt][2]+bc0), gelu_tanh(acc[nt][3]+bc1));
        }
        cp_wait();
        __syncthreads();
        gemm_x3(mHiU, mLoU, bHiU, bLoU, oacc, mrow0, ncol0, lane);  // m @ W2[nt4]
        __syncthreads();
        if (nt4 < 3) copyw_async(6+nt4, bHiU, bLoU);   // W1 tile nt4+1
    }

    // final epilogue: out = x2 + g2*(m + b2); x2 re-read (same-thread writes)
#pragma unroll
    for (int nt=0;nt<8;nt++){
        int col = ncol0+8*nt+2*tig;
        float bc0 = __ldg(b2+col), bc1 = __ldg(b2+col+1);
        float2 x0 = *(const float2*)(out + (size_t)(t0+r0)*128 + col);
        float2 x1 = *(const float2*)(out + (size_t)(t0+r1)*128 + col);
        float o00 = fmaf(g2, oacc[nt][0]+bc0, x0.x);
        float o01 = fmaf(g2, oacc[nt][1]+bc1, x0.y);
        float o10 = fmaf(g2, oacc[nt][2]+bc0, x1.x);
        float o11 = fmaf(g2, oacc[nt][3]+bc1, x1.y);
        *(float2*)(out + (size_t)(t0+r0)*128 + col) = make_float2(o00,o01);
        *(float2*)(out + (size_t)(t0+r1)*128 + col) = make_float2(o10,o11);
    }
}

// ---------------- launch ----------------------------------------------------
extern "C" void kernel_launch(void* const* d_in, const int* in_sizes, int n_in,
                              void* d_out, int out_size)
{
    (void)in_sizes; (void)n_in; (void)out_size;
    const float* F[28];
    for (int i=0;i<28;i++) F[i] = (const float*)d_in[i];
    float* out = (float*)d_out;

    const int K1_SMEM  = 4*TILE_B + 512;             // 139776
    const int K34_SMEM = 6*TILE_B;                   // 208896
    cudaFuncSetAttribute(k1_gates, cudaFuncAttributeMaxDynamicSharedMemorySize, K1_SMEM);
    cudaFuncSetAttribute(k34,      cudaFuncAttributeMaxDynamicSharedMemorySize, K34_SMEM);
    cudaFuncSetAttribute(k2_carry, cudaFuncAttributeMaxDynamicSharedMemorySize, 65536);

    k_prepw<<<13,256>>>(F[8], F[11], F[13], F[16], F[24], F[26]);
    k_affine<<<1,256>>>(F[1], F[2],F[3],F[4],F[5],F[6],F[7],
                              F[18],F[19],F[20],F[21],F[22],F[23]);
    k_nop<<<1,32>>>();   // pad: makes k1_gates the 4th launch (ncu capture slot)
    k1_gates<<<512,NTHR,K1_SMEM>>>(F[0], F[9], F[10], F[12], F[14], F[15]);
    k2_carry<<<dim3(BSZ,2),128,65536>>>();
    k34<<<512,NTHR,K34_SMEM>>>(F[0], F[17], F[25], F[27], out);
}